// round 13
// baseline (speedup 1.0000x reference)
#include <cuda_runtime.h>
#include <cuda_bf16.h>
#include <cstdint>

#define NN 50000
#define EE 800000
#define BB 50
#define LL 7
#define NSCAN_BLK 49

// ---------------- scratch (device globals; no allocations) ----------------
// g_cursor must be zero at entry each call (re-zeroed by scatter_fix).
// Row NN of g_h0h/g_hA/g_hB is a dummy all-zero row (gather out-of-range target).
__device__ __nv_bfloat16  g_h0h[(NN + 1) * 32];
__device__ __nv_bfloat162 g_hA[(NN + 1) * 32];
__device__ __nv_bfloat162 g_hB[(NN + 1) * 32];
__device__ __nv_bfloat16  g_z[NN * 64];          // aggregated z (128B rows)
__device__ __nv_bfloat16  g_Whi[LL * 2 * 4096];  // pre-split weights, transposed [f][c]
__device__ __nv_bfloat16  g_Wlo[LL * 2 * 4096];
__device__ int   g_rowptr[NN + 1];
__device__ int   g_rowptr2[NN + 1];
__device__ int   g_cursor[NN];
__device__ int   g_rank[EE];
__device__ int   g_csr[EE];
__device__ int   g_bsum[64];
__device__ float g_pool[BB * 64];
__device__ int   g_start[BB];
__device__ int   g_end[BB];

typedef unsigned long long u64;
__device__ __forceinline__ uint32_t smem_to_u32(const void* p) {
    uint32_t a;
    asm("{ .reg .u64 t; cvta.to.shared.u64 t, %1; cvt.u32.u64 %0, t; }" : "=r"(a) : "l"(p));
    return a;
}
__device__ __forceinline__ u64 add2(u64 a, u64 b) {
    u64 d; asm("add.rn.f32x2 %0,%1,%2;" : "=l"(d) : "l"(a), "l"(b)); return d;
}
__device__ __forceinline__ u64 bf2f2(uint32_t u) {   // bf16x2 -> packed f32x2 (exact)
    uint32_t lo = u << 16, hi = u & 0xFFFF0000u;
    u64 r; asm("mov.b64 %0,{%1,%2};" : "=l"(r) : "r"(lo), "r"(hi)); return r;
}
__device__ __forceinline__ float2 unpk(u64 v) {
    float2 f; asm("mov.b64 {%0,%1},%2;" : "=f"(f.x), "=f"(f.y) : "l"(v)); return f;
}
__device__ __forceinline__ u64 shfl_xor64(u64 v, int m) {
    uint32_t lo, hi;
    asm("mov.b64 {%0,%1},%2;" : "=r"(lo), "=r"(hi) : "l"(v));
    lo = __shfl_xor_sync(0xffffffffu, lo, m);
    hi = __shfl_xor_sync(0xffffffffu, hi, m);
    u64 r; asm("mov.b64 %0,{%1,%2};" : "=l"(r) : "r"(lo), "r"(hi)); return r;
}
__device__ __forceinline__ uint32_t pkbf(u64 acc) {
    float2 f = unpk(acc);
    __nv_bfloat162 b = __float22bfloat162_rn(f);
    return *(uint32_t*)&b;
}
__device__ __forceinline__ float2 f2add(float2 a, float2 b) { a.x += b.x; a.y += b.y; return a; }

// ---------------- mma.sync helpers ----------------
__device__ __forceinline__ void ldsm_x4(uint32_t r[4], uint32_t addr) {
    asm volatile("ldmatrix.sync.aligned.m8n8.x4.shared.b16 {%0,%1,%2,%3}, [%4];"
        : "=r"(r[0]), "=r"(r[1]), "=r"(r[2]), "=r"(r[3]) : "r"(addr));
}
__device__ __forceinline__ void ldsm_x2(uint32_t r[2], uint32_t addr) {
    asm volatile("ldmatrix.sync.aligned.m8n8.x2.shared.b16 {%0,%1}, [%2];"
        : "=r"(r[0]), "=r"(r[1]) : "r"(addr));
}
__device__ __forceinline__ void mma16816(float d[4], const uint32_t a[4], const uint32_t b[2]) {
    asm volatile(
        "mma.sync.aligned.m16n8k16.row.col.f32.bf16.bf16.f32 "
        "{%0,%1,%2,%3}, {%4,%5,%6,%7}, {%8,%9}, {%0,%1,%2,%3};"
        : "+f"(d[0]), "+f"(d[1]), "+f"(d[2]), "+f"(d[3])
        : "r"(a[0]), "r"(a[1]), "r"(a[2]), "r"(a[3]), "r"(b[0]), "r"(b[1]));
}

// ---------------- launch 1: init + h0 + histogram + weight pre-split ----------------
__global__ void fused_init(const float* __restrict__ x, const float* __restrict__ pos,
                           const int* __restrict__ batch, const int* __restrict__ dst,
                           const float* __restrict__ W1f, const float* __restrict__ W1r,
                           const float* __restrict__ W2) {
    int i = blockIdx.x * blockDim.x + threadIdx.x;
    if (i < NN * 32) {
        int v = i >> 5, c = i & 31;
        float val = (c < 29) ? x[v * 29 + c] : pos[v * 3 + (c - 29)];
        g_h0h[i] = __float2bfloat16_rn(val);
    }
    if (i < EE) g_rank[i] = atomicAdd(&g_cursor[dst[i]], 1);
    if (i < NN) {
        int bi = __ldg(&batch[i]);
        if (i == 0 || __ldg(&batch[i - 1]) != bi) g_start[bi] = i;
        if (i == NN - 1 || __ldg(&batch[i + 1]) != bi) g_end[bi] = i + 1;
    }
    if (i < 2 * LL * 4096) {   // weight pre-split, transposed [f][c]
        int l = i >> 13, m = (i >> 12) & 1, fc = i & 4095;
        int f = fc >> 6, c = fc & 63;
        float w = 0.f;
        if (m == 0) {
            if (l == 0) { if (c < 32) w = __ldg(&W1f[c * 64 + f]); }
            else w = __ldg(&W1r[(size_t)(l - 1) * 4096 + c * 64 + f]);
        } else {
            w = __ldg(&W2[(size_t)l * 4096 + c * 64 + f]);
        }
        __nv_bfloat16 hi = __float2bfloat16_rn(w);
        g_Whi[i] = hi;
        g_Wlo[i] = __float2bfloat16_rn(w - __bfloat162float(hi));
    }
    if (i < 32) {   // dummy zero rows at index NN
        g_h0h[NN * 32 + i] = __float2bfloat16_rn(0.f);
        __nv_bfloat162 z2 = __float22bfloat162_rn(make_float2(0.f, 0.f));
        g_hA[NN * 32 + i] = z2;
        g_hB[NN * 32 + i] = z2;
    }
    if (i == 0) g_rowptr[0] = 0;
    if (i < BB * 64) g_pool[i] = 0.f;
}

// ---------------- launch 2: per-block scan of degrees ----------------
__global__ void scanA_kernel() {
    __shared__ int wsum[32];
    int i = blockIdx.x * 1024 + threadIdx.x;
    int lane = threadIdx.x & 31, wid = threadIdx.x >> 5;
    int xx = (i < NN) ? g_cursor[i] : 0;
    #pragma unroll
    for (int o = 1; o < 32; o <<= 1) {
        int y = __shfl_up_sync(0xffffffffu, xx, o);
        if (lane >= o) xx += y;
    }
    if (lane == 31) wsum[wid] = xx;
    __syncthreads();
    if (wid == 0) {
        int s = wsum[lane];
        #pragma unroll
        for (int o = 1; o < 32; o <<= 1) {
            int y = __shfl_up_sync(0xffffffffu, s, o);
            if (lane >= o) s += y;
        }
        wsum[lane] = s;
    }
    __syncthreads();
    int incl = xx + (wid ? wsum[wid - 1] : 0);
    if (i < NN) g_rowptr[i + 1] = incl;
    if (threadIdx.x == 1023) g_bsum[blockIdx.x] = incl;
}

// ---------------- launch 3: scatter + rowptr finalize + cursor re-zero ----------------
__global__ void scatter_fix(const int* __restrict__ src, const int* __restrict__ dst) {
    __shared__ int sb[NSCAN_BLK + 1];
    if (threadIdx.x < NSCAN_BLK) sb[threadIdx.x + 1] = g_bsum[threadIdx.x];
    __syncthreads();
    if (threadIdx.x == 0) {
        int run = 0;
        #pragma unroll
        for (int k = 0; k < NSCAN_BLK; k++) { int t = sb[k + 1]; sb[k] = run; run += t; }
    }
    __syncthreads();
    int e = blockIdx.x * blockDim.x + threadIdx.x;
    if (e <= NN) {
        int add = (e > 0) ? sb[(e - 1) >> 10] : 0;
        g_rowptr2[e] = g_rowptr[e] + add;
    }
    if (e < EE) {
        int d = dst[e];
        int base = g_rowptr[d] + ((d > 0) ? sb[(d - 1) >> 10] : 0);
        g_csr[base + g_rank[e]] = src[e];
    }
    if (e < NN) g_cursor[e] = 0;
}

// ---------------- gather: 8 lanes/row, 4 rows concurrent, 8 nodes/warp ----------------
// 782 blocks x 8 warps = single wave. Self row preloaded into slot-0 accumulator;
// out-of-range batch slots redirect to dummy zero row NN via one SEL.
template <int C>
__global__ void __launch_bounds__(256, 6) gather_kernel(const void* __restrict__ h_in_v) {
    __shared__ int sidx_all[8][260];
    int* sidx = sidx_all[threadIdx.x >> 5];
    const int lane = threadIdx.x & 31;
    const int slot = lane >> 3, q = lane & 7;
    const int vbase = (blockIdx.x * 8 + (threadIdx.x >> 5)) * 8;

    int rp[9];
    #pragma unroll
    for (int k = 0; k < 9; k++) {
        int v = vbase + k; if (v > NN) v = NN;
        rp[k] = __ldg(&g_rowptr2[v]);
    }
    const int e0 = rp[0];
    const int span = rp[8] - e0;
    const int cap = (span < 256) ? span : 256;
    for (int k = lane; k < cap; k += 32) sidx[k] = __ldg(&g_csr[e0 + k]);
    __syncwarp();

    #pragma unroll 1
    for (int n = 0; n < 8; n++) {
        int v = vbase + n;
        if (v >= NN) break;
        int b0 = rp[n] - e0;
        int deg = rp[n + 1] - rp[n];

        if (C == 64) {
            const uint4* hp = (const uint4*)h_in_v;
            uint4 rs = make_uint4(0, 0, 0, 0);
            if (slot == 0) rs = __ldg(hp + (size_t)v * 8 + q);
            u64 a0 = bf2f2(rs.x), a1 = bf2f2(rs.y), a2 = bf2f2(rs.z), a3 = bf2f2(rs.w);
            if (rp[n + 1] - e0 <= cap) {
                #pragma unroll 2
                for (int j0 = 0; j0 < deg; j0 += 4) {
                    int j = j0 + slot;
                    int sv = sidx[b0 + j];          // in-bounds (<260); junk discarded by SEL
                    int idx = (j < deg) ? sv : NN;  // NN = zero row
                    uint4 r = __ldg(hp + (size_t)idx * 8 + q);
                    a0 = add2(a0, bf2f2(r.x));
                    a1 = add2(a1, bf2f2(r.y));
                    a2 = add2(a2, bf2f2(r.z));
                    a3 = add2(a3, bf2f2(r.w));
                }
            } else {
                for (int j0 = 0; j0 < deg; j0 += 4) {
                    int j = j0 + slot;
                    int idx = (j < deg) ? __ldg(&g_csr[rp[n] + j]) : NN;
                    uint4 r = __ldg(hp + (size_t)idx * 8 + q);
                    a0 = add2(a0, bf2f2(r.x));
                    a1 = add2(a1, bf2f2(r.y));
                    a2 = add2(a2, bf2f2(r.z));
                    a3 = add2(a3, bf2f2(r.w));
                }
            }
            #pragma unroll
            for (int m = 8; m <= 16; m <<= 1) {
                a0 = add2(a0, shfl_xor64(a0, m));
                a1 = add2(a1, shfl_xor64(a1, m));
                a2 = add2(a2, shfl_xor64(a2, m));
                a3 = add2(a3, shfl_xor64(a3, m));
            }
            if (slot == 0) {
                uint4 o = make_uint4(pkbf(a0), pkbf(a1), pkbf(a2), pkbf(a3));
                ((uint4*)g_z)[(size_t)v * 8 + q] = o;
            }
        } else {
            const uint2* hp = (const uint2*)h_in_v;
            uint2 rs = make_uint2(0, 0);
            if (slot == 0) rs = __ldg(hp + (size_t)v * 8 + q);
            u64 a0 = bf2f2(rs.x), a1 = bf2f2(rs.y);
            if (rp[n + 1] - e0 <= cap) {
                #pragma unroll 2
                for (int j0 = 0; j0 < deg; j0 += 4) {
                    int j = j0 + slot;
                    int sv = sidx[b0 + j];
                    int idx = (j < deg) ? sv : NN;
                    uint2 r = __ldg(hp + (size_t)idx * 8 + q);
                    a0 = add2(a0, bf2f2(r.x));
                    a1 = add2(a1, bf2f2(r.y));
                }
            } else {
                for (int j0 = 0; j0 < deg; j0 += 4) {
                    int j = j0 + slot;
                    int idx = (j < deg) ? __ldg(&g_csr[rp[n] + j]) : NN;
                    uint2 r = __ldg(hp + (size_t)idx * 8 + q);
                    a0 = add2(a0, bf2f2(r.x));
                    a1 = add2(a1, bf2f2(r.y));
                }
            }
            #pragma unroll
            for (int m = 8; m <= 16; m <<= 1) {
                a0 = add2(a0, shfl_xor64(a0, m));
                a1 = add2(a1, shfl_xor64(a1, m));
            }
            if (slot == 0) {
                uint2 o = make_uint2(pkbf(a0), pkbf(a1));
                ((uint2*)g_z)[(size_t)v * 16 + q] = o;
            }
        }
    }
}

// ---------------- MLP via mma.sync (one CTA = 128 nodes, 8 warps x 16) ----------------
#define OFF_ZT   0
#define OFF_W1HI 18432
#define OFF_W1LO 27648
#define OFF_W2HI 36864
#define OFF_W2LO 46080
#define OFF_B1   55296
#define OFF_B2   55552
#define MLP_SMEM 55808

template <int KCH>
__device__ __forceinline__ void gemv16(uint32_t a_base, uint32_t whi, uint32_t wlo,
                                       float acc[8][4], int lane) {
    uint32_t a[KCH][4];
    uint32_t arow = a_base + (lane & 15) * 144 + ((lane >> 4) << 4);
    #pragma unroll
    for (int kc = 0; kc < KCH; kc++) ldsm_x4(a[kc], arow + kc * 32);
    uint32_t bro = (lane & 7) * 144 + ((lane & 8) ? 16 : 0);
    #pragma unroll
    for (int nc = 0; nc < 8; nc++) {
        #pragma unroll
        for (int i = 0; i < 4; i++) acc[nc][i] = 0.f;
        #pragma unroll
        for (int kc = 0; kc < KCH; kc++) {
            uint32_t bh[2], bl[2];
            ldsm_x2(bh, whi + bro + nc * 1152 + kc * 32);
            mma16816(acc[nc], a[kc], bh);
            ldsm_x2(bl, wlo + bro + nc * 1152 + kc * 32);
            mma16816(acc[nc], a[kc], bl);
        }
    }
}

template <int C, bool RELU_OUT, bool LAST>
__global__ void __launch_bounds__(256) mlp_mma(
    const uint4* __restrict__ w1hi, const uint4* __restrict__ w1lo,
    const uint4* __restrict__ w2hi, const uint4* __restrict__ w2lo,
    const float* __restrict__ b1, const float* __restrict__ b2,
    __nv_bfloat162* __restrict__ h_out, const int* __restrict__ batch)
{
    extern __shared__ char smem[];
    const uint32_t sb = smem_to_u32(smem);
    const int tid = threadIdx.x, wid = tid >> 5, lane = tid & 31;
    const int vbase = blockIdx.x * 128;
    const int wrow = wid * 16;

    // stage pre-split weights (512 uint4 per tile)
    for (int i = tid; i < 512; i += 256) {
        int f = i >> 3, j = i & 7;
        uint32_t d = f * 144 + j * 16;
        *(uint4*)(smem + OFF_W1HI + d) = __ldg(w1hi + i);
        *(uint4*)(smem + OFF_W1LO + d) = __ldg(w1lo + i);
        *(uint4*)(smem + OFF_W2HI + d) = __ldg(w2hi + i);
        *(uint4*)(smem + OFF_W2LO + d) = __ldg(w2lo + i);
    }
    if (tid < 64) {
        ((float*)(smem + OFF_B1))[tid] = __ldg(&b1[tid]);
        ((float*)(smem + OFF_B2))[tid] = __ldg(&b2[tid]);
    }

    // stage z rows (zero tail rows)
    constexpr int BPR = C / 8;
    for (int i = tid; i < 128 * BPR; i += 256) {
        int row = i / BPR, j = i % BPR;
        int v = vbase + row;
        uint4 val = make_uint4(0, 0, 0, 0);
        if (v < NN) val = __ldg((const uint4*)g_z + (size_t)v * 8 + j);
        *(uint4*)(smem + OFF_ZT + row * 144 + j * 16) = val;
    }
    __syncthreads();

    float acc[8][4];
    const uint32_t abase = sb + OFF_ZT + wrow * 144;

    // ---- GEMV1: t = relu(z @ W1 + b1) ----
    gemv16<C / 16>(abase, sb + OFF_W1HI, sb + OFF_W1LO, acc, lane);
    {
        const float* b1s = (const float*)(smem + OFF_B1);
        int r0off = (wrow + (lane >> 2)) * 144;
        int cb = 2 * (lane & 3);
        #pragma unroll
        for (int nc = 0; nc < 8; nc++) {
            int n0 = nc * 8 + cb;
            float bx = b1s[n0], by = b1s[n0 + 1];
            __nv_bfloat162 p0 = __float22bfloat162_rn(
                make_float2(fmaxf(acc[nc][0] + bx, 0.f), fmaxf(acc[nc][1] + by, 0.f)));
            __nv_bfloat162 p1 = __float22bfloat162_rn(
                make_float2(fmaxf(acc[nc][2] + bx, 0.f), fmaxf(acc[nc][3] + by, 0.f)));
            *(uint32_t*)(smem + OFF_ZT + r0off + n0 * 2) = *(uint32_t*)&p0;
            *(uint32_t*)(smem + OFF_ZT + r0off + 8 * 144 + n0 * 2) = *(uint32_t*)&p1;
        }
    }
    __syncwarp();

    // ---- GEMV2: o = t @ W2 + b2 ----
    gemv16<4>(abase, sb + OFF_W2HI, sb + OFF_W2LO, acc, lane);
    {
        const float* b2s = (const float*)(smem + OFF_B2);
        int r0 = wrow + (lane >> 2);
        int v0 = vbase + r0, v1 = v0 + 8;
        int cb = 2 * (lane & 3);
        if (LAST) {
            int vA = vbase + wrow;
            bool uni = (vA + 15 < NN) && (__ldg(&batch[vA]) == __ldg(&batch[vA + 15]));
            if (uni) {
                int g = __ldg(&batch[vA]);
                float sx[8], sy[8];
                #pragma unroll
                for (int nc = 0; nc < 8; nc++) {
                    int n0 = nc * 8 + cb;
                    float bx = b2s[n0], by = b2s[n0 + 1];
                    sx[nc] = acc[nc][0] + acc[nc][2] + 2.f * bx;
                    sy[nc] = acc[nc][1] + acc[nc][3] + 2.f * by;
                }
                #pragma unroll
                for (int m = 4; m <= 16; m <<= 1) {
                    #pragma unroll
                    for (int nc = 0; nc < 8; nc++) {
                        sx[nc] += __shfl_xor_sync(0xffffffffu, sx[nc], m);
                        sy[nc] += __shfl_xor_sync(0xffffffffu, sy[nc], m);
                    }
                }
                if ((lane >> 2) == 0) {
                    #pragma unroll
                    for (int nc = 0; nc < 8; nc++) {
                        int n0 = nc * 8 + cb;
                        atomicAdd((float2*)&g_pool[g * 64 + n0], make_float2(sx[nc], sy[nc]));
                    }
                }
            } else {
                int gb0 = (v0 < NN) ? __ldg(&batch[v0]) : 0;
                int gb1 = (v1 < NN) ? __ldg(&batch[v1]) : 0;
                #pragma unroll
                for (int nc = 0; nc < 8; nc++) {
                    int n0 = nc * 8 + cb;
                    float bx = b2s[n0], by = b2s[n0 + 1];
                    if (v0 < NN)
                        atomicAdd((float2*)&g_pool[gb0 * 64 + n0],
                                  make_float2(acc[nc][0] + bx, acc[nc][1] + by));
                    if (v1 < NN)
                        atomicAdd((float2*)&g_pool[gb1 * 64 + n0],
                                  make_float2(acc[nc][2] + bx, acc[nc][3] + by));
                }
            }
        } else {
            #pragma unroll
            for (int nc = 0; nc < 8; nc++) {
                int n0 = nc * 8 + cb;
                float bx = b2s[n0], by = b2s[n0 + 1];
                float x0 = acc[nc][0] + bx, y0 = acc[nc][1] + by;
                float x1 = acc[nc][2] + bx, y1 = acc[nc][3] + by;
                if (RELU_OUT) {
                    x0 = fmaxf(x0, 0.f); y0 = fmaxf(y0, 0.f);
                    x1 = fmaxf(x1, 0.f); y1 = fmaxf(y1, 0.f);
                }
                __nv_bfloat162 p0 = __float22bfloat162_rn(make_float2(x0, y0));
                __nv_bfloat162 p1 = __float22bfloat162_rn(make_float2(x1, y1));
                if (v0 < NN) *((uint32_t*)h_out + (size_t)v0 * 32 + (n0 >> 1)) = *(uint32_t*)&p0;
                if (v1 < NN) *((uint32_t*)h_out + (size_t)v1 * 32 + (n0 >> 1)) = *(uint32_t*)&p1;
            }
        }
    }
}

// ---------------- final linear ----------------
__global__ void final_kernel(const float* __restrict__ lin_w,
                             const float* __restrict__ lin_b,
                             float* __restrict__ out) {
    int gtid = blockIdx.x * blockDim.x + threadIdx.x;
    int g = gtid >> 5, lane = threadIdx.x & 31;
    if (g >= BB) return;
    float s = g_pool[g * 64 + lane] * __ldg(&lin_w[lane]) +
              g_pool[g * 64 + 32 + lane] * __ldg(&lin_w[32 + lane]);
    #pragma unroll
    for (int o = 16; o; o >>= 1) s += __shfl_xor_sync(0xffffffffu, s, o);
    if (lane == 0) {
        float cnt = (float)(g_end[g] - g_start[g]);
        out[g] = s / fmaxf(cnt, 1.f) + lin_b[0];
    }
}

// ---------------- launch ----------------
extern "C" void kernel_launch(void* const* d_in, const int* in_sizes, int n_in,
                              void* d_out, int out_size) {
    const float* x     = (const float*)d_in[0];
    const float* pos   = (const float*)d_in[1];
    const int*   ei    = (const int*)d_in[2];
    const int*   batch = (const int*)d_in[3];
    const float* W1f   = (const float*)d_in[4];
    const float* W1r   = (const float*)d_in[5];
    const float* b1    = (const float*)d_in[6];
    const float* W2    = (const float*)d_in[7];
    const float* b2    = (const float*)d_in[8];
    const float* lin_w = (const float*)d_in[9];
    const float* lin_b = (const float*)d_in[10];
    float* out = (float*)d_out;

    const int* src = ei;
    const int* dst = ei + EE;

    void *h0h, *hA, *hB, *whi, *wlo;
    cudaGetSymbolAddress(&h0h, g_h0h);
    cudaGetSymbolAddress(&hA, g_hA);
    cudaGetSymbolAddress(&hB, g_hB);
    cudaGetSymbolAddress(&whi, g_Whi);
    cudaGetSymbolAddress(&wlo, g_Wlo);

    cudaFuncSetAttribute((const void*)mlp_mma<32, true,  false>, cudaFuncAttributeMaxDynamicSharedMemorySize, MLP_SMEM);
    cudaFuncSetAttribute((const void*)mlp_mma<64, true,  false>, cudaFuncAttributeMaxDynamicSharedMemorySize, MLP_SMEM);
    cudaFuncSetAttribute((const void*)mlp_mma<64, false, true>,  cudaFuncAttributeMaxDynamicSharedMemorySize, MLP_SMEM);

    fused_init<<<(NN * 32 + 255) / 256, 256>>>(x, pos, batch, dst, W1f, W1r, W2);
    scanA_kernel<<<NSCAN_BLK, 1024>>>();
    scatter_fix<<<(EE + 255) / 256, 256>>>(src, dst);

    const int GB = (NN + 63) / 64;      // 8 warps x 8 nodes -> 782 blocks (single wave)
    const int MB = (NN + 127) / 128;

    const uint4* WHI = (const uint4*)whi;
    const uint4* WLO = (const uint4*)wlo;

    gather_kernel<32><<<GB, 256>>>(h0h);
    mlp_mma<32, true, false><<<MB, 256, MLP_SMEM>>>(
        WHI + 0, WLO + 0, WHI + 512, WLO + 512, b1, b2, (__nv_bfloat162*)hA, batch);

    void* cur = hA;
    void* nxt = hB;
    for (int l = 1; l < LL; l++) {
        const uint4* w1h = WHI + (size_t)(l * 2) * 512;
        const uint4* w1l = WLO + (size_t)(l * 2) * 512;
        const uint4* w2h = WHI + (size_t)(l * 2 + 1) * 512;
        const uint4* w2l = WLO + (size_t)(l * 2 + 1) * 512;
        gather_kernel<64><<<GB, 256>>>(cur);
        if (l < LL - 1) {
            mlp_mma<64, true, false><<<MB, 256, MLP_SMEM>>>(
                w1h, w1l, w2h, w2l, b1 + l * 64, b2 + l * 64, (__nv_bfloat162*)nxt, batch);
            void* t = cur; cur = nxt; nxt = t;
        } else {
            mlp_mma<64, false, true><<<MB, 256, MLP_SMEM>>>(
                w1h, w1l, w2h, w2l, b1 + l * 64, b2 + l * 64, (__nv_bfloat162*)nxt, batch);
        }
    }

    final_kernel<<<(BB * 32 + 255) / 256, 256>>>(lin_w, lin_b, out);
}

// round 14
// speedup vs baseline: 1.0093x; 1.0093x over previous
#include <cuda_runtime.h>
#include <cuda_bf16.h>
#include <cstdint>

#define NN 50000
#define EE 800000
#define BB 50
#define LL 7
#define NSCAN_BLK 49

// ---------------- scratch (device globals; no allocations) ----------------
// g_cursor must be zero at entry each call (re-zeroed by scatter_fix).
// Row NN of h buffers is a dummy all-zero row (gather out-of-range target).
__device__ __nv_bfloat16  g_h0h[(NN + 1) * 32];
__device__ __nv_bfloat162 g_hA[(NN + 1) * 32];
__device__ __nv_bfloat162 g_hB[(NN + 1) * 32];
__device__ __nv_bfloat16  g_z[NN * 64];
__device__ __nv_bfloat16  g_Whi[LL * 2 * 4096];
__device__ __nv_bfloat16  g_Wlo[LL * 2 * 4096];
__device__ int   g_rowptr[NN + 1];
__device__ int   g_rowptr2[NN + 1];
__device__ int   g_cursor[NN];
__device__ int   g_rank[EE];
__device__ int   g_csr[EE + 16];     // +16 pad: depth-4 gather may probe past end
__device__ int   g_bsum[64];
__device__ float g_pool[BB * 64];
__device__ int   g_start[BB];
__device__ int   g_end[BB];

typedef unsigned long long u64;
__device__ __forceinline__ uint32_t smem_to_u32(const void* p) {
    uint32_t a;
    asm("{ .reg .u64 t; cvta.to.shared.u64 t, %1; cvt.u32.u64 %0, t; }" : "=r"(a) : "l"(p));
    return a;
}
__device__ __forceinline__ u64 add2(u64 a, u64 b) {
    u64 d; asm("add.rn.f32x2 %0,%1,%2;" : "=l"(d) : "l"(a), "l"(b)); return d;
}
__device__ __forceinline__ u64 bf2f2(uint32_t u) {
    uint32_t lo = u << 16, hi = u & 0xFFFF0000u;
    u64 r; asm("mov.b64 %0,{%1,%2};" : "=l"(r) : "r"(lo), "r"(hi)); return r;
}
__device__ __forceinline__ float2 unpk(u64 v) {
    float2 f; asm("mov.b64 {%0,%1},%2;" : "=f"(f.x), "=f"(f.y) : "l"(v)); return f;
}
__device__ __forceinline__ u64 shfl_xor64(u64 v, int m) {
    uint32_t lo, hi;
    asm("mov.b64 {%0,%1},%2;" : "=r"(lo), "=r"(hi) : "l"(v));
    lo = __shfl_xor_sync(0xffffffffu, lo, m);
    hi = __shfl_xor_sync(0xffffffffu, hi, m);
    u64 r; asm("mov.b64 %0,{%1,%2};" : "=l"(r) : "r"(lo), "r"(hi)); return r;
}
__device__ __forceinline__ uint32_t pkbf(u64 acc) {
    float2 f = unpk(acc);
    __nv_bfloat162 b = __float22bfloat162_rn(f);
    return *(uint32_t*)&b;
}
__device__ __forceinline__ float2 f2add(float2 a, float2 b) { a.x += b.x; a.y += b.y; return a; }

// ---------------- mma.sync helpers ----------------
__device__ __forceinline__ void ldsm_x4(uint32_t r[4], uint32_t addr) {
    asm volatile("ldmatrix.sync.aligned.m8n8.x4.shared.b16 {%0,%1,%2,%3}, [%4];"
        : "=r"(r[0]), "=r"(r[1]), "=r"(r[2]), "=r"(r[3]) : "r"(addr));
}
__device__ __forceinline__ void ldsm_x2(uint32_t r[2], uint32_t addr) {
    asm volatile("ldmatrix.sync.aligned.m8n8.x2.shared.b16 {%0,%1}, [%2];"
        : "=r"(r[0]), "=r"(r[1]) : "r"(addr));
}
__device__ __forceinline__ void mma16816(float d[4], const uint32_t a[4], const uint32_t b[2]) {
    asm volatile(
        "mma.sync.aligned.m16n8k16.row.col.f32.bf16.bf16.f32 "
        "{%0,%1,%2,%3}, {%4,%5,%6,%7}, {%8,%9}, {%0,%1,%2,%3};"
        : "+f"(d[0]), "+f"(d[1]), "+f"(d[2]), "+f"(d[3])
        : "r"(a[0]), "r"(a[1]), "r"(a[2]), "r"(a[3]), "r"(b[0]), "r"(b[1]));
}

// ---------------- launch 1: init + h0 + histogram + weight pre-split ----------------
__global__ void fused_init(const float* __restrict__ x, const float* __restrict__ pos,
                           const int* __restrict__ batch, const int* __restrict__ dst,
                           const float* __restrict__ W1f, const float* __restrict__ W1r,
                           const float* __restrict__ W2) {
    int i = blockIdx.x * blockDim.x + threadIdx.x;
    if (i < NN * 32) {
        int v = i >> 5, c = i & 31;
        float val = (c < 29) ? x[v * 29 + c] : pos[v * 3 + (c - 29)];
        g_h0h[i] = __float2bfloat16_rn(val);
    }
    if (i < EE) g_rank[i] = atomicAdd(&g_cursor[dst[i]], 1);
    if (i < NN) {
        int bi = __ldg(&batch[i]);
        if (i == 0 || __ldg(&batch[i - 1]) != bi) g_start[bi] = i;
        if (i == NN - 1 || __ldg(&batch[i + 1]) != bi) g_end[bi] = i + 1;
    }
    if (i < 2 * LL * 4096) {
        int l = i >> 13, m = (i >> 12) & 1, fc = i & 4095;
        int f = fc >> 6, c = fc & 63;
        float w = 0.f;
        if (m == 0) {
            if (l == 0) { if (c < 32) w = __ldg(&W1f[c * 64 + f]); }
            else w = __ldg(&W1r[(size_t)(l - 1) * 4096 + c * 64 + f]);
        } else {
            w = __ldg(&W2[(size_t)l * 4096 + c * 64 + f]);
        }
        __nv_bfloat16 hi = __float2bfloat16_rn(w);
        g_Whi[i] = hi;
        g_Wlo[i] = __float2bfloat16_rn(w - __bfloat162float(hi));
    }
    if (i < 32) {
        g_h0h[NN * 32 + i] = __float2bfloat16_rn(0.f);
        __nv_bfloat162 z2 = __float22bfloat162_rn(make_float2(0.f, 0.f));
        g_hA[NN * 32 + i] = z2;
        g_hB[NN * 32 + i] = z2;
    }
    if (i == 0) g_rowptr[0] = 0;
    if (i < BB * 64) g_pool[i] = 0.f;
}

// ---------------- launch 2: per-block scan of degrees ----------------
__global__ void scanA_kernel() {
    __shared__ int wsum[32];
    int i = blockIdx.x * 1024 + threadIdx.x;
    int lane = threadIdx.x & 31, wid = threadIdx.x >> 5;
    int xx = (i < NN) ? g_cursor[i] : 0;
    #pragma unroll
    for (int o = 1; o < 32; o <<= 1) {
        int y = __shfl_up_sync(0xffffffffu, xx, o);
        if (lane >= o) xx += y;
    }
    if (lane == 31) wsum[wid] = xx;
    __syncthreads();
    if (wid == 0) {
        int s = wsum[lane];
        #pragma unroll
        for (int o = 1; o < 32; o <<= 1) {
            int y = __shfl_up_sync(0xffffffffu, s, o);
            if (lane >= o) s += y;
        }
        wsum[lane] = s;
    }
    __syncthreads();
    int incl = xx + (wid ? wsum[wid - 1] : 0);
    if (i < NN) g_rowptr[i + 1] = incl;
    if (threadIdx.x == 1023) g_bsum[blockIdx.x] = incl;
}

// ---------------- launch 3: scatter + rowptr finalize + cursor re-zero ----------------
__global__ void scatter_fix(const int* __restrict__ src, const int* __restrict__ dst) {
    __shared__ int sb[NSCAN_BLK + 1];
    if (threadIdx.x < NSCAN_BLK) sb[threadIdx.x + 1] = g_bsum[threadIdx.x];
    __syncthreads();
    if (threadIdx.x == 0) {
        int run = 0;
        #pragma unroll
        for (int k = 0; k < NSCAN_BLK; k++) { int t = sb[k + 1]; sb[k] = run; run += t; }
    }
    __syncthreads();
    int e = blockIdx.x * blockDim.x + threadIdx.x;
    if (e <= NN) {
        int add = (e > 0) ? sb[(e - 1) >> 10] : 0;
        g_rowptr2[e] = g_rowptr[e] + add;
    }
    if (e < EE) {
        int d = dst[e];
        int base = g_rowptr[d] + ((d > 0) ? sb[(d - 1) >> 10] : 0);
        g_csr[base + g_rank[e]] = src[e];
    }
    if (e < NN) g_cursor[e] = 0;
}

// ---------------- gather: 8 lanes/row, depth-4 pipelined (16 edges/iter) ----------------
// 8 nodes/warp, 782 blocks. Out-of-range slots steered to zero row NN via SEL;
// sidx padded to 288 and g_csr padded +16 so probe reads stay in bounds.
template <int C>
__global__ void __launch_bounds__(256, 5) gather_kernel(const void* __restrict__ h_in_v) {
    __shared__ int sidx_all[8][288];
    int* sidx = sidx_all[threadIdx.x >> 5];
    const int lane = threadIdx.x & 31;
    const int slot = lane >> 3, q = lane & 7;
    const int vbase = (blockIdx.x * 8 + (threadIdx.x >> 5)) * 8;

    int rp[9];
    #pragma unroll
    for (int k = 0; k < 9; k++) {
        int v = vbase + k; if (v > NN) v = NN;
        rp[k] = __ldg(&g_rowptr2[v]);
    }
    const int e0 = rp[0];
    const int span = rp[8] - e0;
    const int cap = (span < 256) ? span : 256;
    for (int k = lane; k < cap; k += 32) sidx[k] = __ldg(&g_csr[e0 + k]);
    __syncwarp();

    #pragma unroll 1
    for (int n = 0; n < 8; n++) {
        int v = vbase + n;
        if (v >= NN) break;
        int b0 = rp[n] - e0;
        int deg = rp[n + 1] - rp[n];
        bool fast = (rp[n + 1] - e0 <= cap);

        if (C == 64) {
            const uint4* hp = (const uint4*)h_in_v;
            uint4 rs = make_uint4(0, 0, 0, 0);
            if (slot == 0) rs = __ldg(hp + (size_t)v * 8 + q);
            u64 a0 = bf2f2(rs.x), a1 = bf2f2(rs.y), a2 = bf2f2(rs.z), a3 = bf2f2(rs.w);
            if (fast) {
                #pragma unroll 1
                for (int j0 = 0; j0 < deg; j0 += 16) {
                    int j = j0 + slot;
                    // 4 independent loads in flight before any accumulate
                    int i0 = (j      < deg) ? sidx[b0 + j]      : NN;
                    int i1 = (j + 4  < deg) ? sidx[b0 + j + 4]  : NN;
                    int i2 = (j + 8  < deg) ? sidx[b0 + j + 8]  : NN;
                    int i3 = (j + 12 < deg) ? sidx[b0 + j + 12] : NN;
                    uint4 r0 = __ldg(hp + (size_t)i0 * 8 + q);
                    uint4 r1 = __ldg(hp + (size_t)i1 * 8 + q);
                    uint4 r2 = __ldg(hp + (size_t)i2 * 8 + q);
                    uint4 r3 = __ldg(hp + (size_t)i3 * 8 + q);
                    a0 = add2(add2(a0, bf2f2(r0.x)), add2(bf2f2(r1.x), add2(bf2f2(r2.x), bf2f2(r3.x))));
                    a1 = add2(add2(a1, bf2f2(r0.y)), add2(bf2f2(r1.y), add2(bf2f2(r2.y), bf2f2(r3.y))));
                    a2 = add2(add2(a2, bf2f2(r0.z)), add2(bf2f2(r1.z), add2(bf2f2(r2.z), bf2f2(r3.z))));
                    a3 = add2(add2(a3, bf2f2(r0.w)), add2(bf2f2(r1.w), add2(bf2f2(r2.w), bf2f2(r3.w))));
                }
            } else {
                const int* cp = g_csr + rp[n];
                #pragma unroll 1
                for (int j0 = 0; j0 < deg; j0 += 16) {
                    int j = j0 + slot;
                    int i0 = (j      < deg) ? __ldg(cp + j)      : NN;
                    int i1 = (j + 4  < deg) ? __ldg(cp + j + 4)  : NN;
                    int i2 = (j + 8  < deg) ? __ldg(cp + j + 8)  : NN;
                    int i3 = (j + 12 < deg) ? __ldg(cp + j + 12) : NN;
                    uint4 r0 = __ldg(hp + (size_t)i0 * 8 + q);
                    uint4 r1 = __ldg(hp + (size_t)i1 * 8 + q);
                    uint4 r2 = __ldg(hp + (size_t)i2 * 8 + q);
                    uint4 r3 = __ldg(hp + (size_t)i3 * 8 + q);
                    a0 = add2(add2(a0, bf2f2(r0.x)), add2(bf2f2(r1.x), add2(bf2f2(r2.x), bf2f2(r3.x))));
                    a1 = add2(add2(a1, bf2f2(r0.y)), add2(bf2f2(r1.y), add2(bf2f2(r2.y), bf2f2(r3.y))));
                    a2 = add2(add2(a2, bf2f2(r0.z)), add2(bf2f2(r1.z), add2(bf2f2(r2.z), bf2f2(r3.z))));
                    a3 = add2(add2(a3, bf2f2(r0.w)), add2(bf2f2(r1.w), add2(bf2f2(r2.w), bf2f2(r3.w))));
                }
            }
            #pragma unroll
            for (int m = 8; m <= 16; m <<= 1) {
                a0 = add2(a0, shfl_xor64(a0, m));
                a1 = add2(a1, shfl_xor64(a1, m));
                a2 = add2(a2, shfl_xor64(a2, m));
                a3 = add2(a3, shfl_xor64(a3, m));
            }
            if (slot == 0) {
                uint4 o = make_uint4(pkbf(a0), pkbf(a1), pkbf(a2), pkbf(a3));
                ((uint4*)g_z)[(size_t)v * 8 + q] = o;
            }
        } else {
            const uint2* hp = (const uint2*)h_in_v;
            uint2 rs = make_uint2(0, 0);
            if (slot == 0) rs = __ldg(hp + (size_t)v * 8 + q);
            u64 a0 = bf2f2(rs.x), a1 = bf2f2(rs.y);
            if (fast) {
                #pragma unroll 1
                for (int j0 = 0; j0 < deg; j0 += 16) {
                    int j = j0 + slot;
                    int i0 = (j      < deg) ? sidx[b0 + j]      : NN;
                    int i1 = (j + 4  < deg) ? sidx[b0 + j + 4]  : NN;
                    int i2 = (j + 8  < deg) ? sidx[b0 + j + 8]  : NN;
                    int i3 = (j + 12 < deg) ? sidx[b0 + j + 12] : NN;
                    uint2 r0 = __ldg(hp + (size_t)i0 * 8 + q);
                    uint2 r1 = __ldg(hp + (size_t)i1 * 8 + q);
                    uint2 r2 = __ldg(hp + (size_t)i2 * 8 + q);
                    uint2 r3 = __ldg(hp + (size_t)i3 * 8 + q);
                    a0 = add2(add2(a0, bf2f2(r0.x)), add2(bf2f2(r1.x), add2(bf2f2(r2.x), bf2f2(r3.x))));
                    a1 = add2(add2(a1, bf2f2(r0.y)), add2(bf2f2(r1.y), add2(bf2f2(r2.y), bf2f2(r3.y))));
                }
            } else {
                const int* cp = g_csr + rp[n];
                #pragma unroll 1
                for (int j0 = 0; j0 < deg; j0 += 16) {
                    int j = j0 + slot;
                    int i0 = (j      < deg) ? __ldg(cp + j)      : NN;
                    int i1 = (j + 4  < deg) ? __ldg(cp + j + 4)  : NN;
                    int i2 = (j + 8  < deg) ? __ldg(cp + j + 8)  : NN;
                    int i3 = (j + 12 < deg) ? __ldg(cp + j + 12) : NN;
                    uint2 r0 = __ldg(hp + (size_t)i0 * 8 + q);
                    uint2 r1 = __ldg(hp + (size_t)i1 * 8 + q);
                    uint2 r2 = __ldg(hp + (size_t)i2 * 8 + q);
                    uint2 r3 = __ldg(hp + (size_t)i3 * 8 + q);
                    a0 = add2(add2(a0, bf2f2(r0.x)), add2(bf2f2(r1.x), add2(bf2f2(r2.x), bf2f2(r3.x))));
                    a1 = add2(add2(a1, bf2f2(r0.y)), add2(bf2f2(r1.y), add2(bf2f2(r2.y), bf2f2(r3.y))));
                }
            }
            #pragma unroll
            for (int m = 8; m <= 16; m <<= 1) {
                a0 = add2(a0, shfl_xor64(a0, m));
                a1 = add2(a1, shfl_xor64(a1, m));
            }
            if (slot == 0) {
                uint2 o = make_uint2(pkbf(a0), pkbf(a1));
                ((uint2*)g_z)[(size_t)v * 16 + q] = o;
            }
        }
    }
}

// ---------------- MLP via mma.sync (one CTA = 128 nodes, 8 warps x 16) ----------------
#define OFF_ZT   0
#define OFF_W1HI 18432
#define OFF_W1LO 27648
#define OFF_W2HI 36864
#define OFF_W2LO 46080
#define OFF_B1   55296
#define OFF_B2   55552
#define MLP_SMEM 55808

template <int KCH>
__device__ __forceinline__ void gemv16(uint32_t a_base, uint32_t whi, uint32_t wlo,
                                       float acc[8][4], int lane) {
    uint32_t a[KCH][4];
    uint32_t arow = a_base + (lane & 15) * 144 + ((lane >> 4) << 4);
    #pragma unroll
    for (int kc = 0; kc < KCH; kc++) ldsm_x4(a[kc], arow + kc * 32);
    uint32_t bro = (lane & 7) * 144 + ((lane & 8) ? 16 : 0);
    #pragma unroll
    for (int nc = 0; nc < 8; nc++) {
        #pragma unroll
        for (int i = 0; i < 4; i++) acc[nc][i] = 0.f;
        #pragma unroll
        for (int kc = 0; kc < KCH; kc++) {
            uint32_t bh[2], bl[2];
            ldsm_x2(bh, whi + bro + nc * 1152 + kc * 32);
            mma16816(acc[nc], a[kc], bh);
            ldsm_x2(bl, wlo + bro + nc * 1152 + kc * 32);
            mma16816(acc[nc], a[kc], bl);
        }
    }
}

template <int C, bool RELU_OUT, bool LAST>
__global__ void __launch_bounds__(256) mlp_mma(
    const uint4* __restrict__ w1hi, const uint4* __restrict__ w1lo,
    const uint4* __restrict__ w2hi, const uint4* __restrict__ w2lo,
    const float* __restrict__ b1, const float* __restrict__ b2,
    __nv_bfloat162* __restrict__ h_out, const int* __restrict__ batch)
{
    extern __shared__ char smem[];
    const uint32_t sb = smem_to_u32(smem);
    const int tid = threadIdx.x, wid = tid >> 5, lane = tid & 31;
    const int vbase = blockIdx.x * 128;
    const int wrow = wid * 16;

    for (int i = tid; i < 512; i += 256) {
        int f = i >> 3, j = i & 7;
        uint32_t d = f * 144 + j * 16;
        *(uint4*)(smem + OFF_W1HI + d) = __ldg(w1hi + i);
        *(uint4*)(smem + OFF_W1LO + d) = __ldg(w1lo + i);
        *(uint4*)(smem + OFF_W2HI + d) = __ldg(w2hi + i);
        *(uint4*)(smem + OFF_W2LO + d) = __ldg(w2lo + i);
    }
    if (tid < 64) {
        ((float*)(smem + OFF_B1))[tid] = __ldg(&b1[tid]);
        ((float*)(smem + OFF_B2))[tid] = __ldg(&b2[tid]);
    }

    constexpr int BPR = C / 8;
    for (int i = tid; i < 128 * BPR; i += 256) {
        int row = i / BPR, j = i % BPR;
        int v = vbase + row;
        uint4 val = make_uint4(0, 0, 0, 0);
        if (v < NN) val = __ldg((const uint4*)g_z + (size_t)v * 8 + j);
        *(uint4*)(smem + OFF_ZT + row * 144 + j * 16) = val;
    }
    __syncthreads();

    float acc[8][4];
    const uint32_t abase = sb + OFF_ZT + wrow * 144;

    gemv16<C / 16>(abase, sb + OFF_W1HI, sb + OFF_W1LO, acc, lane);
    {
        const float* b1s = (const float*)(smem + OFF_B1);
        int r0off = (wrow + (lane >> 2)) * 144;
        int cb = 2 * (lane & 3);
        #pragma unroll
        for (int nc = 0; nc < 8; nc++) {
            int n0 = nc * 8 + cb;
            float bx = b1s[n0], by = b1s[n0 + 1];
            __nv_bfloat162 p0 = __float22bfloat162_rn(
                make_float2(fmaxf(acc[nc][0] + bx, 0.f), fmaxf(acc[nc][1] + by, 0.f)));
            __nv_bfloat162 p1 = __float22bfloat162_rn(
                make_float2(fmaxf(acc[nc][2] + bx, 0.f), fmaxf(acc[nc][3] + by, 0.f)));
            *(uint32_t*)(smem + OFF_ZT + r0off + n0 * 2) = *(uint32_t*)&p0;
            *(uint32_t*)(smem + OFF_ZT + r0off + 8 * 144 + n0 * 2) = *(uint32_t*)&p1;
        }
    }
    __syncwarp();

    gemv16<4>(abase, sb + OFF_W2HI, sb + OFF_W2LO, acc, lane);
    {
        const float* b2s = (const float*)(smem + OFF_B2);
        int r0 = wrow + (lane >> 2);
        int v0 = vbase + r0, v1 = v0 + 8;
        int cb = 2 * (lane & 3);
        if (LAST) {
            int vA = vbase + wrow;
            bool uni = (vA + 15 < NN) && (__ldg(&batch[vA]) == __ldg(&batch[vA + 15]));
            if (uni) {
                int g = __ldg(&batch[vA]);
                float sx[8], sy[8];
                #pragma unroll
                for (int nc = 0; nc < 8; nc++) {
                    int n0 = nc * 8 + cb;
                    sx[nc] = acc[nc][0] + acc[nc][2] + 2.f * b2s[n0];
                    sy[nc] = acc[nc][1] + acc[nc][3] + 2.f * b2s[n0 + 1];
                }
                #pragma unroll
                for (int m = 4; m <= 16; m <<= 1) {
                    #pragma unroll
                    for (int nc = 0; nc < 8; nc++) {
                        sx[nc] += __shfl_xor_sync(0xffffffffu, sx[nc], m);
                        sy[nc] += __shfl_xor_sync(0xffffffffu, sy[nc], m);
                    }
                }
                if ((lane >> 2) == 0) {
                    #pragma unroll
                    for (int nc = 0; nc < 8; nc++) {
                        int n0 = nc * 8 + cb;
                        atomicAdd((float2*)&g_pool[g * 64 + n0], make_float2(sx[nc], sy[nc]));
                    }
                }
            } else {
                int gb0 = (v0 < NN) ? __ldg(&batch[v0]) : 0;
                int gb1 = (v1 < NN) ? __ldg(&batch[v1]) : 0;
                #pragma unroll
                for (int nc = 0; nc < 8; nc++) {
                    int n0 = nc * 8 + cb;
                    float bx = b2s[n0], by = b2s[n0 + 1];
                    if (v0 < NN)
                        atomicAdd((float2*)&g_pool[gb0 * 64 + n0],
                                  make_float2(acc[nc][0] + bx, acc[nc][1] + by));
                    if (v1 < NN)
                        atomicAdd((float2*)&g_pool[gb1 * 64 + n0],
                                  make_float2(acc[nc][2] + bx, acc[nc][3] + by));
                }
            }
        } else {
            #pragma unroll
            for (int nc = 0; nc < 8; nc++) {
                int n0 = nc * 8 + cb;
                float bx = b2s[n0], by = b2s[n0 + 1];
                float x0 = acc[nc][0] + bx, y0 = acc[nc][1] + by;
                float x1 = acc[nc][2] + bx, y1 = acc[nc][3] + by;
                if (RELU_OUT) {
                    x0 = fmaxf(x0, 0.f); y0 = fmaxf(y0, 0.f);
                    x1 = fmaxf(x1, 0.f); y1 = fmaxf(y1, 0.f);
                }
                __nv_bfloat162 p0 = __float22bfloat162_rn(make_float2(x0, y0));
                __nv_bfloat162 p1 = __float22bfloat162_rn(make_float2(x1, y1));
                if (v0 < NN) *((uint32_t*)h_out + (size_t)v0 * 32 + (n0 >> 1)) = *(uint32_t*)&p0;
                if (v1 < NN) *((uint32_t*)h_out + (size_t)v1 * 32 + (n0 >> 1)) = *(uint32_t*)&p1;
            }
        }
    }
}

// ---------------- final linear ----------------
__global__ void final_kernel(const float* __restrict__ lin_w,
                             const float* __restrict__ lin_b,
                             float* __restrict__ out) {
    int gtid = blockIdx.x * blockDim.x + threadIdx.x;
    int g = gtid >> 5, lane = threadIdx.x & 31;
    if (g >= BB) return;
    float s = g_pool[g * 64 + lane] * __ldg(&lin_w[lane]) +
              g_pool[g * 64 + 32 + lane] * __ldg(&lin_w[32 + lane]);
    #pragma unroll
    for (int o = 16; o; o >>= 1) s += __shfl_xor_sync(0xffffffffu, s, o);
    if (lane == 0) {
        float cnt = (float)(g_end[g] - g_start[g]);
        out[g] = s / fmaxf(cnt, 1.f) + lin_b[0];
    }
}

// ---------------- launch ----------------
extern "C" void kernel_launch(void* const* d_in, const int* in_sizes, int n_in,
                              void* d_out, int out_size) {
    const float* x     = (const float*)d_in[0];
    const float* pos   = (const float*)d_in[1];
    const int*   ei    = (const int*)d_in[2];
    const int*   batch = (const int*)d_in[3];
    const float* W1f   = (const float*)d_in[4];
    const float* W1r   = (const float*)d_in[5];
    const float* b1    = (const float*)d_in[6];
    const float* W2    = (const float*)d_in[7];
    const float* b2    = (const float*)d_in[8];
    const float* lin_w = (const float*)d_in[9];
    const float* lin_b = (const float*)d_in[10];
    float* out = (float*)d_out;

    const int* src = ei;
    const int* dst = ei + EE;

    void *h0h, *hA, *hB, *whi, *wlo;
    cudaGetSymbolAddress(&h0h, g_h0h);
    cudaGetSymbolAddress(&hA, g_hA);
    cudaGetSymbolAddress(&hB, g_hB);
    cudaGetSymbolAddress(&whi, g_Whi);
    cudaGetSymbolAddress(&wlo, g_Wlo);

    cudaFuncSetAttribute((const void*)mlp_mma<32, true,  false>, cudaFuncAttributeMaxDynamicSharedMemorySize, MLP_SMEM);
    cudaFuncSetAttribute((const void*)mlp_mma<64, true,  false>, cudaFuncAttributeMaxDynamicSharedMemorySize, MLP_SMEM);
    cudaFuncSetAttribute((const void*)mlp_mma<64, false, true>,  cudaFuncAttributeMaxDynamicSharedMemorySize, MLP_SMEM);

    fused_init<<<(NN * 32 + 255) / 256, 256>>>(x, pos, batch, dst, W1f, W1r, W2);
    scanA_kernel<<<NSCAN_BLK, 1024>>>();
    scatter_fix<<<(EE + 255) / 256, 256>>>(src, dst);

    const int GB = (NN + 63) / 64;
    const int MB = (NN + 127) / 128;

    const uint4* WHI = (const uint4*)whi;
    const uint4* WLO = (const uint4*)wlo;

    gather_kernel<32><<<GB, 256>>>(h0h);
    mlp_mma<32, true, false><<<MB, 256, MLP_SMEM>>>(
        WHI + 0, WLO + 0, WHI + 512, WLO + 512, b1, b2, (__nv_bfloat162*)hA, batch);

    void* cur = hA;
    void* nxt = hB;
    for (int l = 1; l < LL; l++) {
        const uint4* w1h = WHI + (size_t)(l * 2) * 512;
        const uint4* w1l = WLO + (size_t)(l * 2) * 512;
        const uint4* w2h = WHI + (size_t)(l * 2 + 1) * 512;
        const uint4* w2l = WLO + (size_t)(l * 2 + 1) * 512;
        gather_kernel<64><<<GB, 256>>>(cur);
        if (l < LL - 1) {
            mlp_mma<64, true, false><<<MB, 256, MLP_SMEM>>>(
                w1h, w1l, w2h, w2l, b1 + l * 64, b2 + l * 64, (__nv_bfloat162*)nxt, batch);
            void* t = cur; cur = nxt; nxt = t;
        } else {
            mlp_mma<64, false, true><<<MB, 256, MLP_SMEM>>>(
                w1h, w1l, w2h, w2l, b1 + l * 64, b2 + l * 64, (__nv_bfloat162*)nxt, batch);
        }
    }

    final_kernel<<<(BB * 32 + 255) / 256, 256>>>(lin_w, lin_b, out);
}

// round 15
// speedup vs baseline: 1.0725x; 1.0626x over previous
#include <cuda_runtime.h>
#include <cuda_bf16.h>
#include <cstdint>

#define NN 50000
#define EE 800000
#define BB 50
#define LL 7
#define NSCAN_BLK 49

// ---------------- scratch (device globals; no allocations) ----------------
// g_cursor must be zero at entry each call (re-zeroed by scatter_fix).
// Row NN of h buffers is a dummy all-zero row (gather out-of-range target).
__device__ __nv_bfloat16  g_h0h[(NN + 1) * 32];
__device__ __nv_bfloat162 g_hA[(NN + 1) * 32];
__device__ __nv_bfloat162 g_hB[(NN + 1) * 32];
__device__ __nv_bfloat16  g_z[NN * 64];
__device__ __nv_bfloat16  g_Whi[LL * 2 * 4096];
__device__ __nv_bfloat16  g_Wlo[LL * 2 * 4096];
__device__ int   g_rowptr[NN + 1];
__device__ int   g_rowptr2[NN + 1];
__device__ int   g_cursor[NN];
__device__ int   g_rank[EE];
__device__ int   g_csr[EE + 16];     // +16 pad: steered probes may read past end
__device__ int   g_bsum[64];
__device__ float g_pool[BB * 64];
__device__ int   g_start[BB];
__device__ int   g_end[BB];

typedef unsigned long long u64;
__device__ __forceinline__ uint32_t smem_to_u32(const void* p) {
    uint32_t a;
    asm("{ .reg .u64 t; cvta.to.shared.u64 t, %1; cvt.u32.u64 %0, t; }" : "=r"(a) : "l"(p));
    return a;
}
__device__ __forceinline__ u64 add2(u64 a, u64 b) {
    u64 d; asm("add.rn.f32x2 %0,%1,%2;" : "=l"(d) : "l"(a), "l"(b)); return d;
}
__device__ __forceinline__ u64 bf2f2(uint32_t u) {
    uint32_t lo = u << 16, hi = u & 0xFFFF0000u;
    u64 r; asm("mov.b64 %0,{%1,%2};" : "=l"(r) : "r"(lo), "r"(hi)); return r;
}
__device__ __forceinline__ float2 unpk(u64 v) {
    float2 f; asm("mov.b64 {%0,%1},%2;" : "=f"(f.x), "=f"(f.y) : "l"(v)); return f;
}
__device__ __forceinline__ u64 shfl_xor64(u64 v, int m) {
    uint32_t lo, hi;
    asm("mov.b64 {%0,%1},%2;" : "=r"(lo), "=r"(hi) : "l"(v));
    lo = __shfl_xor_sync(0xffffffffu, lo, m);
    hi = __shfl_xor_sync(0xffffffffu, hi, m);
    u64 r; asm("mov.b64 %0,{%1,%2};" : "=l"(r) : "r"(lo), "r"(hi)); return r;
}
__device__ __forceinline__ uint32_t pkbf(u64 acc) {
    float2 f = unpk(acc);
    __nv_bfloat162 b = __float22bfloat162_rn(f);
    return *(uint32_t*)&b;
}
__device__ __forceinline__ float2 f2add(float2 a, float2 b) { a.x += b.x; a.y += b.y; return a; }

// ---------------- mma.sync helpers ----------------
__device__ __forceinline__ void ldsm_x4(uint32_t r[4], uint32_t addr) {
    asm volatile("ldmatrix.sync.aligned.m8n8.x4.shared.b16 {%0,%1,%2,%3}, [%4];"
        : "=r"(r[0]), "=r"(r[1]), "=r"(r[2]), "=r"(r[3]) : "r"(addr));
}
__device__ __forceinline__ void ldsm_x2(uint32_t r[2], uint32_t addr) {
    asm volatile("ldmatrix.sync.aligned.m8n8.x2.shared.b16 {%0,%1}, [%2];"
        : "=r"(r[0]), "=r"(r[1]) : "r"(addr));
}
__device__ __forceinline__ void mma16816(float d[4], const uint32_t a[4], const uint32_t b[2]) {
    asm volatile(
        "mma.sync.aligned.m16n8k16.row.col.f32.bf16.bf16.f32 "
        "{%0,%1,%2,%3}, {%4,%5,%6,%7}, {%8,%9}, {%0,%1,%2,%3};"
        : "+f"(d[0]), "+f"(d[1]), "+f"(d[2]), "+f"(d[3])
        : "r"(a[0]), "r"(a[1]), "r"(a[2]), "r"(a[3]), "r"(b[0]), "r"(b[1]));
}

// ---------------- launch 1: init + h0 + histogram + weight pre-split ----------------
__global__ void fused_init(const float* __restrict__ x, const float* __restrict__ pos,
                           const int* __restrict__ batch, const int* __restrict__ dst,
                           const float* __restrict__ W1f, const float* __restrict__ W1r,
                           const float* __restrict__ W2) {
    int i = blockIdx.x * blockDim.x + threadIdx.x;
    if (i < NN * 32) {
        int v = i >> 5, c = i & 31;
        float val = (c < 29) ? x[v * 29 + c] : pos[v * 3 + (c - 29)];
        g_h0h[i] = __float2bfloat16_rn(val);
    }
    if (i < EE) g_rank[i] = atomicAdd(&g_cursor[dst[i]], 1);
    if (i < NN) {
        int bi = __ldg(&batch[i]);
        if (i == 0 || __ldg(&batch[i - 1]) != bi) g_start[bi] = i;
        if (i == NN - 1 || __ldg(&batch[i + 1]) != bi) g_end[bi] = i + 1;
    }
    if (i < 2 * LL * 4096) {
        int l = i >> 13, m = (i >> 12) & 1, fc = i & 4095;
        int f = fc >> 6, c = fc & 63;
        float w = 0.f;
        if (m == 0) {
            if (l == 0) { if (c < 32) w = __ldg(&W1f[c * 64 + f]); }
            else w = __ldg(&W1r[(size_t)(l - 1) * 4096 + c * 64 + f]);
        } else {
            w = __ldg(&W2[(size_t)l * 4096 + c * 64 + f]);
        }
        __nv_bfloat16 hi = __float2bfloat16_rn(w);
        g_Whi[i] = hi;
        g_Wlo[i] = __float2bfloat16_rn(w - __bfloat162float(hi));
    }
    if (i < 32) {
        g_h0h[NN * 32 + i] = __float2bfloat16_rn(0.f);
        __nv_bfloat162 z2 = __float22bfloat162_rn(make_float2(0.f, 0.f));
        g_hA[NN * 32 + i] = z2;
        g_hB[NN * 32 + i] = z2;
    }
    if (i == 0) g_rowptr[0] = 0;
    if (i < BB * 64) g_pool[i] = 0.f;
}

// ---------------- launch 2: per-block scan of degrees ----------------
__global__ void scanA_kernel() {
    __shared__ int wsum[32];
    int i = blockIdx.x * 1024 + threadIdx.x;
    int lane = threadIdx.x & 31, wid = threadIdx.x >> 5;
    int xx = (i < NN) ? g_cursor[i] : 0;
    #pragma unroll
    for (int o = 1; o < 32; o <<= 1) {
        int y = __shfl_up_sync(0xffffffffu, xx, o);
        if (lane >= o) xx += y;
    }
    if (lane == 31) wsum[wid] = xx;
    __syncthreads();
    if (wid == 0) {
        int s = wsum[lane];
        #pragma unroll
        for (int o = 1; o < 32; o <<= 1) {
            int y = __shfl_up_sync(0xffffffffu, s, o);
            if (lane >= o) s += y;
        }
        wsum[lane] = s;
    }
    __syncthreads();
    int incl = xx + (wid ? wsum[wid - 1] : 0);
    if (i < NN) g_rowptr[i + 1] = incl;
    if (threadIdx.x == 1023) g_bsum[blockIdx.x] = incl;
}

// ---------------- launch 3: scatter + rowptr finalize + cursor re-zero ----------------
__global__ void scatter_fix(const int* __restrict__ src, const int* __restrict__ dst) {
    __shared__ int sb[NSCAN_BLK + 1];
    if (threadIdx.x < NSCAN_BLK) sb[threadIdx.x + 1] = g_bsum[threadIdx.x];
    __syncthreads();
    if (threadIdx.x == 0) {
        int run = 0;
        #pragma unroll
        for (int k = 0; k < NSCAN_BLK; k++) { int t = sb[k + 1]; sb[k] = run; run += t; }
    }
    __syncthreads();
    int e = blockIdx.x * blockDim.x + threadIdx.x;
    if (e <= NN) {
        int add = (e > 0) ? sb[(e - 1) >> 10] : 0;
        g_rowptr2[e] = g_rowptr[e] + add;
    }
    if (e < EE) {
        int d = dst[e];
        int base = g_rowptr[d] + ((d > 0) ? sb[(d - 1) >> 10] : 0);
        g_csr[base + g_rank[e]] = src[e];
    }
    if (e < NN) g_cursor[e] = 0;
}

// ---------------- gather: R12 shape (4 nodes/warp, 1563 blocks, cap 8) ----------------
// 8 lanes per row, 4 edge-slots per iteration; self-row preloaded into slot-0
// accumulator; out-of-range slots steered to zero row NN via SEL.
template <int C>
__global__ void __launch_bounds__(256, 8) gather_kernel(const void* __restrict__ h_in_v) {
    __shared__ int sidx_all[8][260];
    int* sidx = sidx_all[threadIdx.x >> 5];
    const int lane = threadIdx.x & 31;
    const int slot = lane >> 3, q = lane & 7;
    const int vbase = (blockIdx.x * 8 + (threadIdx.x >> 5)) * 4;

    int rp[5];
    #pragma unroll
    for (int k = 0; k < 5; k++) {
        int v = vbase + k; if (v > NN) v = NN;
        rp[k] = __ldg(&g_rowptr2[v]);
    }
    const int e0 = rp[0];
    const int span = rp[4] - e0;
    const int cap = (span < 256) ? span : 256;
    for (int k = lane; k < cap; k += 32) sidx[k] = __ldg(&g_csr[e0 + k]);
    __syncwarp();

    #pragma unroll
    for (int n = 0; n < 4; n++) {
        int v = vbase + n;
        if (v >= NN) break;
        int b0 = rp[n] - e0;
        int deg = rp[n + 1] - rp[n];
        bool fast = (rp[n + 1] - e0 <= cap);

        if (C == 64) {
            const uint4* hp = (const uint4*)h_in_v;
            uint4 rs = make_uint4(0, 0, 0, 0);
            if (slot == 0) rs = __ldg(hp + (size_t)v * 8 + q);
            u64 a0 = bf2f2(rs.x), a1 = bf2f2(rs.y), a2 = bf2f2(rs.z), a3 = bf2f2(rs.w);
            if (fast) {
                #pragma unroll 2
                for (int j0 = 0; j0 < deg; j0 += 4) {
                    int j = j0 + slot;
                    int sv = sidx[b0 + j];          // in-bounds (<260); junk discarded by SEL
                    int idx = (j < deg) ? sv : NN;  // NN = zero row
                    uint4 r = __ldg(hp + (size_t)idx * 8 + q);
                    a0 = add2(a0, bf2f2(r.x));
                    a1 = add2(a1, bf2f2(r.y));
                    a2 = add2(a2, bf2f2(r.z));
                    a3 = add2(a3, bf2f2(r.w));
                }
            } else {
                const int* cp = g_csr + rp[n];
                for (int j0 = 0; j0 < deg; j0 += 4) {
                    int j = j0 + slot;
                    int sv = __ldg(cp + j);
                    int idx = (j < deg) ? sv : NN;
                    uint4 r = __ldg(hp + (size_t)idx * 8 + q);
                    a0 = add2(a0, bf2f2(r.x));
                    a1 = add2(a1, bf2f2(r.y));
                    a2 = add2(a2, bf2f2(r.z));
                    a3 = add2(a3, bf2f2(r.w));
                }
            }
            #pragma unroll
            for (int m = 8; m <= 16; m <<= 1) {
                a0 = add2(a0, shfl_xor64(a0, m));
                a1 = add2(a1, shfl_xor64(a1, m));
                a2 = add2(a2, shfl_xor64(a2, m));
                a3 = add2(a3, shfl_xor64(a3, m));
            }
            if (slot == 0) {
                uint4 o = make_uint4(pkbf(a0), pkbf(a1), pkbf(a2), pkbf(a3));
                ((uint4*)g_z)[(size_t)v * 8 + q] = o;
            }
        } else {
            const uint2* hp = (const uint2*)h_in_v;
            uint2 rs = make_uint2(0, 0);
            if (slot == 0) rs = __ldg(hp + (size_t)v * 8 + q);
            u64 a0 = bf2f2(rs.x), a1 = bf2f2(rs.y);
            if (fast) {
                #pragma unroll 2
                for (int j0 = 0; j0 < deg; j0 += 4) {
                    int j = j0 + slot;
                    int sv = sidx[b0 + j];
                    int idx = (j < deg) ? sv : NN;
                    uint2 r = __ldg(hp + (size_t)idx * 8 + q);
                    a0 = add2(a0, bf2f2(r.x));
                    a1 = add2(a1, bf2f2(r.y));
                }
            } else {
                const int* cp = g_csr + rp[n];
                for (int j0 = 0; j0 < deg; j0 += 4) {
                    int j = j0 + slot;
                    int sv = __ldg(cp + j);
                    int idx = (j < deg) ? sv : NN;
                    uint2 r = __ldg(hp + (size_t)idx * 8 + q);
                    a0 = add2(a0, bf2f2(r.x));
                    a1 = add2(a1, bf2f2(r.y));
                }
            }
            #pragma unroll
            for (int m = 8; m <= 16; m <<= 1) {
                a0 = add2(a0, shfl_xor64(a0, m));
                a1 = add2(a1, shfl_xor64(a1, m));
            }
            if (slot == 0) {
                uint2 o = make_uint2(pkbf(a0), pkbf(a1));
                ((uint2*)g_z)[(size_t)v * 16 + q] = o;
            }
        }
    }
}

// ---------------- MLP via mma.sync (one CTA = 128 nodes, 8 warps x 16) ----------------
#define OFF_ZT   0
#define OFF_W1HI 18432
#define OFF_W1LO 27648
#define OFF_W2HI 36864
#define OFF_W2LO 46080
#define OFF_B1   55296
#define OFF_B2   55552
#define MLP_SMEM 55808

template <int KCH>
__device__ __forceinline__ void gemv16(uint32_t a_base, uint32_t whi, uint32_t wlo,
                                       float acc[8][4], int lane) {
    uint32_t a[KCH][4];
    uint32_t arow = a_base + (lane & 15) * 144 + ((lane >> 4) << 4);
    #pragma unroll
    for (int kc = 0; kc < KCH; kc++) ldsm_x4(a[kc], arow + kc * 32);
    uint32_t bro = (lane & 7) * 144 + ((lane & 8) ? 16 : 0);
    #pragma unroll
    for (int nc = 0; nc < 8; nc++) {
        #pragma unroll
        for (int i = 0; i < 4; i++) acc[nc][i] = 0.f;
        #pragma unroll
        for (int kc = 0; kc < KCH; kc++) {
            uint32_t bh[2], bl[2];
            ldsm_x2(bh, whi + bro + nc * 1152 + kc * 32);
            mma16816(acc[nc], a[kc], bh);
            ldsm_x2(bl, wlo + bro + nc * 1152 + kc * 32);
            mma16816(acc[nc], a[kc], bl);
        }
    }
}

template <int C, bool RELU_OUT, bool LAST>
__global__ void __launch_bounds__(256) mlp_mma(
    const uint4* __restrict__ w1hi, const uint4* __restrict__ w1lo,
    const uint4* __restrict__ w2hi, const uint4* __restrict__ w2lo,
    const float* __restrict__ b1, const float* __restrict__ b2,
    __nv_bfloat162* __restrict__ h_out, const int* __restrict__ batch)
{
    extern __shared__ char smem[];
    const uint32_t sb = smem_to_u32(smem);
    const int tid = threadIdx.x, wid = tid >> 5, lane = tid & 31;
    const int vbase = blockIdx.x * 128;
    const int wrow = wid * 16;

    for (int i = tid; i < 512; i += 256) {
        int f = i >> 3, j = i & 7;
        uint32_t d = f * 144 + j * 16;
        *(uint4*)(smem + OFF_W1HI + d) = __ldg(w1hi + i);
        *(uint4*)(smem + OFF_W1LO + d) = __ldg(w1lo + i);
        *(uint4*)(smem + OFF_W2HI + d) = __ldg(w2hi + i);
        *(uint4*)(smem + OFF_W2LO + d) = __ldg(w2lo + i);
    }
    if (tid < 64) {
        ((float*)(smem + OFF_B1))[tid] = __ldg(&b1[tid]);
        ((float*)(smem + OFF_B2))[tid] = __ldg(&b2[tid]);
    }

    constexpr int BPR = C / 8;
    for (int i = tid; i < 128 * BPR; i += 256) {
        int row = i / BPR, j = i % BPR;
        int v = vbase + row;
        uint4 val = make_uint4(0, 0, 0, 0);
        if (v < NN) val = __ldg((const uint4*)g_z + (size_t)v * 8 + j);
        *(uint4*)(smem + OFF_ZT + row * 144 + j * 16) = val;
    }
    __syncthreads();

    float acc[8][4];
    const uint32_t abase = sb + OFF_ZT + wrow * 144;

    gemv16<C / 16>(abase, sb + OFF_W1HI, sb + OFF_W1LO, acc, lane);
    {
        const float* b1s = (const float*)(smem + OFF_B1);
        int r0off = (wrow + (lane >> 2)) * 144;
        int cb = 2 * (lane & 3);
        #pragma unroll
        for (int nc = 0; nc < 8; nc++) {
            int n0 = nc * 8 + cb;
            float bx = b1s[n0], by = b1s[n0 + 1];
            __nv_bfloat162 p0 = __float22bfloat162_rn(
                make_float2(fmaxf(acc[nc][0] + bx, 0.f), fmaxf(acc[nc][1] + by, 0.f)));
            __nv_bfloat162 p1 = __float22bfloat162_rn(
                make_float2(fmaxf(acc[nc][2] + bx, 0.f), fmaxf(acc[nc][3] + by, 0.f)));
            *(uint32_t*)(smem + OFF_ZT + r0off + n0 * 2) = *(uint32_t*)&p0;
            *(uint32_t*)(smem + OFF_ZT + r0off + 8 * 144 + n0 * 2) = *(uint32_t*)&p1;
        }
    }
    __syncwarp();

    gemv16<4>(abase, sb + OFF_W2HI, sb + OFF_W2LO, acc, lane);
    {
        const float* b2s = (const float*)(smem + OFF_B2);
        int r0 = wrow + (lane >> 2);
        int v0 = vbase + r0, v1 = v0 + 8;
        int cb = 2 * (lane & 3);
        if (LAST) {
            int vA = vbase + wrow;
            bool uni = (vA + 15 < NN) && (__ldg(&batch[vA]) == __ldg(&batch[vA + 15]));
            if (uni) {
                int g = __ldg(&batch[vA]);
                float sx[8], sy[8];
                #pragma unroll
                for (int nc = 0; nc < 8; nc++) {
                    int n0 = nc * 8 + cb;
                    sx[nc] = acc[nc][0] + acc[nc][2] + 2.f * b2s[n0];
                    sy[nc] = acc[nc][1] + acc[nc][3] + 2.f * b2s[n0 + 1];
                }
                #pragma unroll
                for (int m = 4; m <= 16; m <<= 1) {
                    #pragma unroll
                    for (int nc = 0; nc < 8; nc++) {
                        sx[nc] += __shfl_xor_sync(0xffffffffu, sx[nc], m);
                        sy[nc] += __shfl_xor_sync(0xffffffffu, sy[nc], m);
                    }
                }
                if ((lane >> 2) == 0) {
                    #pragma unroll
                    for (int nc = 0; nc < 8; nc++) {
                        int n0 = nc * 8 + cb;
                        atomicAdd((float2*)&g_pool[g * 64 + n0], make_float2(sx[nc], sy[nc]));
                    }
                }
            } else {
                int gb0 = (v0 < NN) ? __ldg(&batch[v0]) : 0;
                int gb1 = (v1 < NN) ? __ldg(&batch[v1]) : 0;
                #pragma unroll
                for (int nc = 0; nc < 8; nc++) {
                    int n0 = nc * 8 + cb;
                    float bx = b2s[n0], by = b2s[n0 + 1];
                    if (v0 < NN)
                        atomicAdd((float2*)&g_pool[gb0 * 64 + n0],
                                  make_float2(acc[nc][0] + bx, acc[nc][1] + by));
                    if (v1 < NN)
                        atomicAdd((float2*)&g_pool[gb1 * 64 + n0],
                                  make_float2(acc[nc][2] + bx, acc[nc][3] + by));
                }
            }
        } else {
            #pragma unroll
            for (int nc = 0; nc < 8; nc++) {
                int n0 = nc * 8 + cb;
                float bx = b2s[n0], by = b2s[n0 + 1];
                float x0 = acc[nc][0] + bx, y0 = acc[nc][1] + by;
                float x1 = acc[nc][2] + bx, y1 = acc[nc][3] + by;
                if (RELU_OUT) {
                    x0 = fmaxf(x0, 0.f); y0 = fmaxf(y0, 0.f);
                    x1 = fmaxf(x1, 0.f); y1 = fmaxf(y1, 0.f);
                }
                __nv_bfloat162 p0 = __float22bfloat162_rn(make_float2(x0, y0));
                __nv_bfloat162 p1 = __float22bfloat162_rn(make_float2(x1, y1));
                if (v0 < NN) *((uint32_t*)h_out + (size_t)v0 * 32 + (n0 >> 1)) = *(uint32_t*)&p0;
                if (v1 < NN) *((uint32_t*)h_out + (size_t)v1 * 32 + (n0 >> 1)) = *(uint32_t*)&p1;
            }
        }
    }
}

// ---------------- final linear ----------------
__global__ void final_kernel(const float* __restrict__ lin_w,
                             const float* __restrict__ lin_b,
                             float* __restrict__ out) {
    int gtid = blockIdx.x * blockDim.x + threadIdx.x;
    int g = gtid >> 5, lane = threadIdx.x & 31;
    if (g >= BB) return;
    float s = g_pool[g * 64 + lane] * __ldg(&lin_w[lane]) +
              g_pool[g * 64 + 32 + lane] * __ldg(&lin_w[32 + lane]);
    #pragma unroll
    for (int o = 16; o; o >>= 1) s += __shfl_xor_sync(0xffffffffu, s, o);
    if (lane == 0) {
        float cnt = (float)(g_end[g] - g_start[g]);
        out[g] = s / fmaxf(cnt, 1.f) + lin_b[0];
    }
}

// ---------------- launch ----------------
extern "C" void kernel_launch(void* const* d_in, const int* in_sizes, int n_in,
                              void* d_out, int out_size) {
    const float* x     = (const float*)d_in[0];
    const float* pos   = (const float*)d_in[1];
    const int*   ei    = (const int*)d_in[2];
    const int*   batch = (const int*)d_in[3];
    const float* W1f   = (const float*)d_in[4];
    const float* W1r   = (const float*)d_in[5];
    const float* b1    = (const float*)d_in[6];
    const float* W2    = (const float*)d_in[7];
    const float* b2    = (const float*)d_in[8];
    const float* lin_w = (const float*)d_in[9];
    const float* lin_b = (const float*)d_in[10];
    float* out = (float*)d_out;

    const int* src = ei;
    const int* dst = ei + EE;

    void *h0h, *hA, *hB, *whi, *wlo;
    cudaGetSymbolAddress(&h0h, g_h0h);
    cudaGetSymbolAddress(&hA, g_hA);
    cudaGetSymbolAddress(&hB, g_hB);
    cudaGetSymbolAddress(&whi, g_Whi);
    cudaGetSymbolAddress(&wlo, g_Wlo);

    cudaFuncSetAttribute((const void*)mlp_mma<32, true,  false>, cudaFuncAttributeMaxDynamicSharedMemorySize, MLP_SMEM);
    cudaFuncSetAttribute((const void*)mlp_mma<64, true,  false>, cudaFuncAttributeMaxDynamicSharedMemorySize, MLP_SMEM);
    cudaFuncSetAttribute((const void*)mlp_mma<64, false, true>,  cudaFuncAttributeMaxDynamicSharedMemorySize, MLP_SMEM);

    fused_init<<<(NN * 32 + 255) / 256, 256>>>(x, pos, batch, dst, W1f, W1r, W2);
    scanA_kernel<<<NSCAN_BLK, 1024>>>();
    scatter_fix<<<(EE + 255) / 256, 256>>>(src, dst);

    const int GB = (NN + 31) / 32;      // 8 warps x 4 nodes -> 1563 blocks
    const int MB = (NN + 127) / 128;

    const uint4* WHI = (const uint4*)whi;
    const uint4* WLO = (const uint4*)wlo;

    gather_kernel<32><<<GB, 256>>>(h0h);
    mlp_mma<32, true, false><<<MB, 256, MLP_SMEM>>>(
        WHI + 0, WLO + 0, WHI + 512, WLO + 512, b1, b2, (__nv_bfloat162*)hA, batch);

    void* cur = hA;
    void* nxt = hB;
    for (int l = 1; l < LL; l++) {
        const uint4* w1h = WHI + (size_t)(l * 2) * 512;
        const uint4* w1l = WLO + (size_t)(l * 2) * 512;
        const uint4* w2h = WHI + (size_t)(l * 2 + 1) * 512;
        const uint4* w2l = WLO + (size_t)(l * 2 + 1) * 512;
        gather_kernel<64><<<GB, 256>>>(cur);
        if (l < LL - 1) {
            mlp_mma<64, true, false><<<MB, 256, MLP_SMEM>>>(
                w1h, w1l, w2h, w2l, b1 + l * 64, b2 + l * 64, (__nv_bfloat162*)nxt, batch);
            void* t = cur; cur = nxt; nxt = t;
        } else {
            mlp_mma<64, false, true><<<MB, 256, MLP_SMEM>>>(
                w1h, w1l, w2h, w2l, b1 + l * 64, b2 + l * 64, (__nv_bfloat162*)nxt, batch);
        }
    }

    final_kernel<<<(BB * 32 + 255) / 256, 256>>>(lin_w, lin_b, out);
}

// round 16
// speedup vs baseline: 1.1402x; 1.0631x over previous
#include <cuda_runtime.h>
#include <cuda_bf16.h>
#include <cstdint>

#define NN 50000
#define EE 800000
#define BB 50
#define LL 7
#define NSCAN_BLK 49

// ---------------- scratch (device globals; no allocations) ----------------
// g_cursor must be zero at entry each call (re-zeroed by scatter_fix).
// Row NN of h buffers is a dummy all-zero row (gather out-of-range target).
__device__ __nv_bfloat16  g_h0h[(NN + 1) * 32];
__device__ __nv_bfloat162 g_hA[(NN + 1) * 32];
__device__ __nv_bfloat162 g_hB[(NN + 1) * 32];
__device__ __nv_bfloat16  g_z[NN * 64];
__device__ __nv_bfloat16  g_Whi[LL * 2 * 4096];
__device__ __nv_bfloat16  g_Wlo[LL * 2 * 4096];
__device__ int   g_rowptr[NN + 1];
__device__ int   g_rowptr2[NN + 1];
__device__ int   g_cursor[NN];
__device__ int   g_rank[EE];
__device__ int   g_csr[EE + 16];     // +16 pad: steered probes may read past end
__device__ int   g_bsum[64];
__device__ float g_pool[BB * 64];
__device__ int   g_start[BB];
__device__ int   g_end[BB];

typedef unsigned long long u64;
__device__ __forceinline__ uint32_t smem_to_u32(const void* p) {
    uint32_t a;
    asm("{ .reg .u64 t; cvta.to.shared.u64 t, %1; cvt.u32.u64 %0, t; }" : "=r"(a) : "l"(p));
    return a;
}
__device__ __forceinline__ u64 add2(u64 a, u64 b) {
    u64 d; asm("add.rn.f32x2 %0,%1,%2;" : "=l"(d) : "l"(a), "l"(b)); return d;
}
__device__ __forceinline__ u64 bf2f2(uint32_t u) {
    uint32_t lo = u << 16, hi = u & 0xFFFF0000u;
    u64 r; asm("mov.b64 %0,{%1,%2};" : "=l"(r) : "r"(lo), "r"(hi)); return r;
}
__device__ __forceinline__ float2 unpk(u64 v) {
    float2 f; asm("mov.b64 {%0,%1},%2;" : "=f"(f.x), "=f"(f.y) : "l"(v)); return f;
}
__device__ __forceinline__ u64 shfl_xor64(u64 v, int m) {
    uint32_t lo, hi;
    asm("mov.b64 {%0,%1},%2;" : "=r"(lo), "=r"(hi) : "l"(v));
    lo = __shfl_xor_sync(0xffffffffu, lo, m);
    hi = __shfl_xor_sync(0xffffffffu, hi, m);
    u64 r; asm("mov.b64 %0,{%1,%2};" : "=l"(r) : "r"(lo), "r"(hi)); return r;
}
__device__ __forceinline__ uint32_t pkbf(u64 acc) {
    float2 f = unpk(acc);
    __nv_bfloat162 b = __float22bfloat162_rn(f);
    return *(uint32_t*)&b;
}
__device__ __forceinline__ float2 f2add(float2 a, float2 b) { a.x += b.x; a.y += b.y; return a; }

// ---------------- mma.sync helpers ----------------
__device__ __forceinline__ void ldsm_x4(uint32_t r[4], uint32_t addr) {
    asm volatile("ldmatrix.sync.aligned.m8n8.x4.shared.b16 {%0,%1,%2,%3}, [%4];"
        : "=r"(r[0]), "=r"(r[1]), "=r"(r[2]), "=r"(r[3]) : "r"(addr));
}
__device__ __forceinline__ void ldsm_x2(uint32_t r[2], uint32_t addr) {
    asm volatile("ldmatrix.sync.aligned.m8n8.x2.shared.b16 {%0,%1}, [%2];"
        : "=r"(r[0]), "=r"(r[1]) : "r"(addr));
}
__device__ __forceinline__ void mma16816(float d[4], const uint32_t a[4], const uint32_t b[2]) {
    asm volatile(
        "mma.sync.aligned.m16n8k16.row.col.f32.bf16.bf16.f32 "
        "{%0,%1,%2,%3}, {%4,%5,%6,%7}, {%8,%9}, {%0,%1,%2,%3};"
        : "+f"(d[0]), "+f"(d[1]), "+f"(d[2]), "+f"(d[3])
        : "r"(a[0]), "r"(a[1]), "r"(a[2]), "r"(a[3]), "r"(b[0]), "r"(b[1]));
}

// ---------------- launch 1: init + h0 + histogram + weight pre-split ----------------
__global__ void fused_init(const float* __restrict__ x, const float* __restrict__ pos,
                           const int* __restrict__ batch, const int* __restrict__ dst,
                           const float* __restrict__ W1f, const float* __restrict__ W1r,
                           const float* __restrict__ W2) {
    int i = blockIdx.x * blockDim.x + threadIdx.x;
    if (i < NN * 32) {
        int v = i >> 5, c = i & 31;
        float val = (c < 29) ? x[v * 29 + c] : pos[v * 3 + (c - 29)];
        g_h0h[i] = __float2bfloat16_rn(val);
    }
    if (i < EE) g_rank[i] = atomicAdd(&g_cursor[dst[i]], 1);
    if (i < NN) {
        int bi = __ldg(&batch[i]);
        if (i == 0 || __ldg(&batch[i - 1]) != bi) g_start[bi] = i;
        if (i == NN - 1 || __ldg(&batch[i + 1]) != bi) g_end[bi] = i + 1;
    }
    if (i < 2 * LL * 4096) {
        int l = i >> 13, m = (i >> 12) & 1, fc = i & 4095;
        int f = fc >> 6, c = fc & 63;
        float w = 0.f;
        if (m == 0) {
            if (l == 0) { if (c < 32) w = __ldg(&W1f[c * 64 + f]); }
            else w = __ldg(&W1r[(size_t)(l - 1) * 4096 + c * 64 + f]);
        } else {
            w = __ldg(&W2[(size_t)l * 4096 + c * 64 + f]);
        }
        __nv_bfloat16 hi = __float2bfloat16_rn(w);
        g_Whi[i] = hi;
        g_Wlo[i] = __float2bfloat16_rn(w - __bfloat162float(hi));
    }
    if (i < 32) {
        g_h0h[NN * 32 + i] = __float2bfloat16_rn(0.f);
        __nv_bfloat162 z2 = __float22bfloat162_rn(make_float2(0.f, 0.f));
        g_hA[NN * 32 + i] = z2;
        g_hB[NN * 32 + i] = z2;
    }
    if (i == 0) g_rowptr[0] = 0;
    if (i < BB * 64) g_pool[i] = 0.f;
}

// ---------------- launch 2: per-block scan of degrees ----------------
__global__ void scanA_kernel() {
    __shared__ int wsum[32];
    int i = blockIdx.x * 1024 + threadIdx.x;
    int lane = threadIdx.x & 31, wid = threadIdx.x >> 5;
    int xx = (i < NN) ? g_cursor[i] : 0;
    #pragma unroll
    for (int o = 1; o < 32; o <<= 1) {
        int y = __shfl_up_sync(0xffffffffu, xx, o);
        if (lane >= o) xx += y;
    }
    if (lane == 31) wsum[wid] = xx;
    __syncthreads();
    if (wid == 0) {
        int s = wsum[lane];
        #pragma unroll
        for (int o = 1; o < 32; o <<= 1) {
            int y = __shfl_up_sync(0xffffffffu, s, o);
            if (lane >= o) s += y;
        }
        wsum[lane] = s;
    }
    __syncthreads();
    int incl = xx + (wid ? wsum[wid - 1] : 0);
    if (i < NN) g_rowptr[i + 1] = incl;
    if (threadIdx.x == 1023) g_bsum[blockIdx.x] = incl;
}

// ---------------- launch 3: scatter + rowptr finalize + cursor re-zero ----------------
__global__ void scatter_fix(const int* __restrict__ src, const int* __restrict__ dst) {
    __shared__ int sb[NSCAN_BLK + 1];
    if (threadIdx.x < NSCAN_BLK) sb[threadIdx.x + 1] = g_bsum[threadIdx.x];
    __syncthreads();
    if (threadIdx.x == 0) {
        int run = 0;
        #pragma unroll
        for (int k = 0; k < NSCAN_BLK; k++) { int t = sb[k + 1]; sb[k] = run; run += t; }
    }
    __syncthreads();
    int e = blockIdx.x * blockDim.x + threadIdx.x;
    if (e <= NN) {
        int add = (e > 0) ? sb[(e - 1) >> 10] : 0;
        g_rowptr2[e] = g_rowptr[e] + add;
    }
    if (e < EE) {
        int d = dst[e];
        int base = g_rowptr[d] + ((d > 0) ? sb[(d - 1) >> 10] : 0);
        g_csr[base + g_rank[e]] = src[e];
    }
    if (e < NN) g_cursor[e] = 0;
}

// ---------------- gather: 2 nodes/warp, 8 lanes/row, 4 edge-slots/iter ----------------
// 3125 blocks x 8 warps = 25000 warps; ~28 regs -> full 64-warp residency and
// fine-grained work-steal balance. Self-row preloaded; steering to zero row NN.
template <int C>
__global__ void __launch_bounds__(256, 8) gather_kernel(const void* __restrict__ h_in_v) {
    __shared__ int sidx_all[8][132];
    int* sidx = sidx_all[threadIdx.x >> 5];
    const int lane = threadIdx.x & 31;
    const int slot = lane >> 3, q = lane & 7;
    const int vbase = (blockIdx.x * 8 + (threadIdx.x >> 5)) * 2;

    int rp[3];
    #pragma unroll
    for (int k = 0; k < 3; k++) {
        int v = vbase + k; if (v > NN) v = NN;
        rp[k] = __ldg(&g_rowptr2[v]);
    }
    const int e0 = rp[0];
    const int span = rp[2] - e0;
    const int cap = (span < 128) ? span : 128;
    for (int k = lane; k < cap; k += 32) sidx[k] = __ldg(&g_csr[e0 + k]);
    __syncwarp();

    #pragma unroll
    for (int n = 0; n < 2; n++) {
        int v = vbase + n;
        if (v >= NN) break;
        int b0 = rp[n] - e0;
        int deg = rp[n + 1] - rp[n];
        bool fast = (rp[n + 1] - e0 <= cap);

        if (C == 64) {
            const uint4* hp = (const uint4*)h_in_v;
            uint4 rs = make_uint4(0, 0, 0, 0);
            if (slot == 0) rs = __ldg(hp + (size_t)v * 8 + q);
            u64 a0 = bf2f2(rs.x), a1 = bf2f2(rs.y), a2 = bf2f2(rs.z), a3 = bf2f2(rs.w);
            if (fast) {
                #pragma unroll 2
                for (int j0 = 0; j0 < deg; j0 += 4) {
                    int j = j0 + slot;
                    int sv = sidx[b0 + j];          // in-bounds (<132); junk discarded by SEL
                    int idx = (j < deg) ? sv : NN;  // NN = zero row
                    uint4 r = __ldg(hp + (size_t)idx * 8 + q);
                    a0 = add2(a0, bf2f2(r.x));
                    a1 = add2(a1, bf2f2(r.y));
                    a2 = add2(a2, bf2f2(r.z));
                    a3 = add2(a3, bf2f2(r.w));
                }
            } else {
                const int* cp = g_csr + rp[n];
                for (int j0 = 0; j0 < deg; j0 += 4) {
                    int j = j0 + slot;
                    int sv = __ldg(cp + j);
                    int idx = (j < deg) ? sv : NN;
                    uint4 r = __ldg(hp + (size_t)idx * 8 + q);
                    a0 = add2(a0, bf2f2(r.x));
                    a1 = add2(a1, bf2f2(r.y));
                    a2 = add2(a2, bf2f2(r.z));
                    a3 = add2(a3, bf2f2(r.w));
                }
            }
            #pragma unroll
            for (int m = 8; m <= 16; m <<= 1) {
                a0 = add2(a0, shfl_xor64(a0, m));
                a1 = add2(a1, shfl_xor64(a1, m));
                a2 = add2(a2, shfl_xor64(a2, m));
                a3 = add2(a3, shfl_xor64(a3, m));
            }
            if (slot == 0) {
                uint4 o = make_uint4(pkbf(a0), pkbf(a1), pkbf(a2), pkbf(a3));
                ((uint4*)g_z)[(size_t)v * 8 + q] = o;
            }
        } else {
            const uint2* hp = (const uint2*)h_in_v;
            uint2 rs = make_uint2(0, 0);
            if (slot == 0) rs = __ldg(hp + (size_t)v * 8 + q);
            u64 a0 = bf2f2(rs.x), a1 = bf2f2(rs.y);
            if (fast) {
                #pragma unroll 2
                for (int j0 = 0; j0 < deg; j0 += 4) {
                    int j = j0 + slot;
                    int sv = sidx[b0 + j];
                    int idx = (j < deg) ? sv : NN;
                    uint2 r = __ldg(hp + (size_t)idx * 8 + q);
                    a0 = add2(a0, bf2f2(r.x));
                    a1 = add2(a1, bf2f2(r.y));
                }
            } else {
                const int* cp = g_csr + rp[n];
                for (int j0 = 0; j0 < deg; j0 += 4) {
                    int j = j0 + slot;
                    int sv = __ldg(cp + j);
                    int idx = (j < deg) ? sv : NN;
                    uint2 r = __ldg(hp + (size_t)idx * 8 + q);
                    a0 = add2(a0, bf2f2(r.x));
                    a1 = add2(a1, bf2f2(r.y));
                }
            }
            #pragma unroll
            for (int m = 8; m <= 16; m <<= 1) {
                a0 = add2(a0, shfl_xor64(a0, m));
                a1 = add2(a1, shfl_xor64(a1, m));
            }
            if (slot == 0) {
                uint2 o = make_uint2(pkbf(a0), pkbf(a1));
                ((uint2*)g_z)[(size_t)v * 16 + q] = o;
            }
        }
    }
}

// ---------------- MLP via mma.sync (one CTA = 128 nodes, 8 warps x 16) ----------------
#define OFF_ZT   0
#define OFF_W1HI 18432
#define OFF_W1LO 27648
#define OFF_W2HI 36864
#define OFF_W2LO 46080
#define OFF_B1   55296
#define OFF_B2   55552
#define MLP_SMEM 55808

template <int KCH>
__device__ __forceinline__ void gemv16(uint32_t a_base, uint32_t whi, uint32_t wlo,
                                       float acc[8][4], int lane) {
    uint32_t a[KCH][4];
    uint32_t arow = a_base + (lane & 15) * 144 + ((lane >> 4) << 4);
    #pragma unroll
    for (int kc = 0; kc < KCH; kc++) ldsm_x4(a[kc], arow + kc * 32);
    uint32_t bro = (lane & 7) * 144 + ((lane & 8) ? 16 : 0);
    #pragma unroll
    for (int nc = 0; nc < 8; nc++) {
        #pragma unroll
        for (int i = 0; i < 4; i++) acc[nc][i] = 0.f;
        #pragma unroll
        for (int kc = 0; kc < KCH; kc++) {
            uint32_t bh[2], bl[2];
            ldsm_x2(bh, whi + bro + nc * 1152 + kc * 32);
            mma16816(acc[nc], a[kc], bh);
            ldsm_x2(bl, wlo + bro + nc * 1152 + kc * 32);
            mma16816(acc[nc], a[kc], bl);
        }
    }
}

template <int C, bool RELU_OUT, bool LAST>
__global__ void __launch_bounds__(256) mlp_mma(
    const uint4* __restrict__ w1hi, const uint4* __restrict__ w1lo,
    const uint4* __restrict__ w2hi, const uint4* __restrict__ w2lo,
    const float* __restrict__ b1, const float* __restrict__ b2,
    __nv_bfloat162* __restrict__ h_out, const int* __restrict__ batch)
{
    extern __shared__ char smem[];
    const uint32_t sb = smem_to_u32(smem);
    const int tid = threadIdx.x, wid = tid >> 5, lane = tid & 31;
    const int vbase = blockIdx.x * 128;
    const int wrow = wid * 16;

    for (int i = tid; i < 512; i += 256) {
        int f = i >> 3, j = i & 7;
        uint32_t d = f * 144 + j * 16;
        *(uint4*)(smem + OFF_W1HI + d) = __ldg(w1hi + i);
        *(uint4*)(smem + OFF_W1LO + d) = __ldg(w1lo + i);
        *(uint4*)(smem + OFF_W2HI + d) = __ldg(w2hi + i);
        *(uint4*)(smem + OFF_W2LO + d) = __ldg(w2lo + i);
    }
    if (tid < 64) {
        ((float*)(smem + OFF_B1))[tid] = __ldg(&b1[tid]);
        ((float*)(smem + OFF_B2))[tid] = __ldg(&b2[tid]);
    }

    constexpr int BPR = C / 8;
    for (int i = tid; i < 128 * BPR; i += 256) {
        int row = i / BPR, j = i % BPR;
        int v = vbase + row;
        uint4 val = make_uint4(0, 0, 0, 0);
        if (v < NN) val = __ldg((const uint4*)g_z + (size_t)v * 8 + j);
        *(uint4*)(smem + OFF_ZT + row * 144 + j * 16) = val;
    }
    __syncthreads();

    float acc[8][4];
    const uint32_t abase = sb + OFF_ZT + wrow * 144;

    gemv16<C / 16>(abase, sb + OFF_W1HI, sb + OFF_W1LO, acc, lane);
    {
        const float* b1s = (const float*)(smem + OFF_B1);
        int r0off = (wrow + (lane >> 2)) * 144;
        int cb = 2 * (lane & 3);
        #pragma unroll
        for (int nc = 0; nc < 8; nc++) {
            int n0 = nc * 8 + cb;
            float bx = b1s[n0], by = b1s[n0 + 1];
            __nv_bfloat162 p0 = __float22bfloat162_rn(
                make_float2(fmaxf(acc[nc][0] + bx, 0.f), fmaxf(acc[nc][1] + by, 0.f)));
            __nv_bfloat162 p1 = __float22bfloat162_rn(
                make_float2(fmaxf(acc[nc][2] + bx, 0.f), fmaxf(acc[nc][3] + by, 0.f)));
            *(uint32_t*)(smem + OFF_ZT + r0off + n0 * 2) = *(uint32_t*)&p0;
            *(uint32_t*)(smem + OFF_ZT + r0off + 8 * 144 + n0 * 2) = *(uint32_t*)&p1;
        }
    }
    __syncwarp();

    gemv16<4>(abase, sb + OFF_W2HI, sb + OFF_W2LO, acc, lane);
    {
        const float* b2s = (const float*)(smem + OFF_B2);
        int r0 = wrow + (lane >> 2);
        int v0 = vbase + r0, v1 = v0 + 8;
        int cb = 2 * (lane & 3);
        if (LAST) {
            int vA = vbase + wrow;
            bool uni = (vA + 15 < NN) && (__ldg(&batch[vA]) == __ldg(&batch[vA + 15]));
            if (uni) {
                int g = __ldg(&batch[vA]);
                float sx[8], sy[8];
                #pragma unroll
                for (int nc = 0; nc < 8; nc++) {
                    int n0 = nc * 8 + cb;
                    sx[nc] = acc[nc][0] + acc[nc][2] + 2.f * b2s[n0];
                    sy[nc] = acc[nc][1] + acc[nc][3] + 2.f * b2s[n0 + 1];
                }
                #pragma unroll
                for (int m = 4; m <= 16; m <<= 1) {
                    #pragma unroll
                    for (int nc = 0; nc < 8; nc++) {
                        sx[nc] += __shfl_xor_sync(0xffffffffu, sx[nc], m);
                        sy[nc] += __shfl_xor_sync(0xffffffffu, sy[nc], m);
                    }
                }
                if ((lane >> 2) == 0) {
                    #pragma unroll
                    for (int nc = 0; nc < 8; nc++) {
                        int n0 = nc * 8 + cb;
                        atomicAdd((float2*)&g_pool[g * 64 + n0], make_float2(sx[nc], sy[nc]));
                    }
                }
            } else {
                int gb0 = (v0 < NN) ? __ldg(&batch[v0]) : 0;
                int gb1 = (v1 < NN) ? __ldg(&batch[v1]) : 0;
                #pragma unroll
                for (int nc = 0; nc < 8; nc++) {
                    int n0 = nc * 8 + cb;
                    float bx = b2s[n0], by = b2s[n0 + 1];
                    if (v0 < NN)
                        atomicAdd((float2*)&g_pool[gb0 * 64 + n0],
                                  make_float2(acc[nc][0] + bx, acc[nc][1] + by));
                    if (v1 < NN)
                        atomicAdd((float2*)&g_pool[gb1 * 64 + n0],
                                  make_float2(acc[nc][2] + bx, acc[nc][3] + by));
                }
            }
        } else {
            #pragma unroll
            for (int nc = 0; nc < 8; nc++) {
                int n0 = nc * 8 + cb;
                float bx = b2s[n0], by = b2s[n0 + 1];
                float x0 = acc[nc][0] + bx, y0 = acc[nc][1] + by;
                float x1 = acc[nc][2] + bx, y1 = acc[nc][3] + by;
                if (RELU_OUT) {
                    x0 = fmaxf(x0, 0.f); y0 = fmaxf(y0, 0.f);
                    x1 = fmaxf(x1, 0.f); y1 = fmaxf(y1, 0.f);
                }
                __nv_bfloat162 p0 = __float22bfloat162_rn(make_float2(x0, y0));
                __nv_bfloat162 p1 = __float22bfloat162_rn(make_float2(x1, y1));
                if (v0 < NN) *((uint32_t*)h_out + (size_t)v0 * 32 + (n0 >> 1)) = *(uint32_t*)&p0;
                if (v1 < NN) *((uint32_t*)h_out + (size_t)v1 * 32 + (n0 >> 1)) = *(uint32_t*)&p1;
            }
        }
    }
}

// ---------------- final linear ----------------
__global__ void final_kernel(const float* __restrict__ lin_w,
                             const float* __restrict__ lin_b,
                             float* __restrict__ out) {
    int gtid = blockIdx.x * blockDim.x + threadIdx.x;
    int g = gtid >> 5, lane = threadIdx.x & 31;
    if (g >= BB) return;
    float s = g_pool[g * 64 + lane] * __ldg(&lin_w[lane]) +
              g_pool[g * 64 + 32 + lane] * __ldg(&lin_w[32 + lane]);
    #pragma unroll
    for (int o = 16; o; o >>= 1) s += __shfl_xor_sync(0xffffffffu, s, o);
    if (lane == 0) {
        float cnt = (float)(g_end[g] - g_start[g]);
        out[g] = s / fmaxf(cnt, 1.f) + lin_b[0];
    }
}

// ---------------- launch ----------------
extern "C" void kernel_launch(void* const* d_in, const int* in_sizes, int n_in,
                              void* d_out, int out_size) {
    const float* x     = (const float*)d_in[0];
    const float* pos   = (const float*)d_in[1];
    const int*   ei    = (const int*)d_in[2];
    const int*   batch = (const int*)d_in[3];
    const float* W1f   = (const float*)d_in[4];
    const float* W1r   = (const float*)d_in[5];
    const float* b1    = (const float*)d_in[6];
    const float* W2    = (const float*)d_in[7];
    const float* b2    = (const float*)d_in[8];
    const float* lin_w = (const float*)d_in[9];
    const float* lin_b = (const float*)d_in[10];
    float* out = (float*)d_out;

    const int* src = ei;
    const int* dst = ei + EE;

    void *h0h, *hA, *hB, *whi, *wlo;
    cudaGetSymbolAddress(&h0h, g_h0h);
    cudaGetSymbolAddress(&hA, g_hA);
    cudaGetSymbolAddress(&hB, g_hB);
    cudaGetSymbolAddress(&whi, g_Whi);
    cudaGetSymbolAddress(&wlo, g_Wlo);

    cudaFuncSetAttribute((const void*)mlp_mma<32, true,  false>, cudaFuncAttributeMaxDynamicSharedMemorySize, MLP_SMEM);
    cudaFuncSetAttribute((const void*)mlp_mma<64, true,  false>, cudaFuncAttributeMaxDynamicSharedMemorySize, MLP_SMEM);
    cudaFuncSetAttribute((const void*)mlp_mma<64, false, true>,  cudaFuncAttributeMaxDynamicSharedMemorySize, MLP_SMEM);

    fused_init<<<(NN * 32 + 255) / 256, 256>>>(x, pos, batch, dst, W1f, W1r, W2);
    scanA_kernel<<<NSCAN_BLK, 1024>>>();
    scatter_fix<<<(EE + 255) / 256, 256>>>(src, dst);

    const int GB = (NN + 15) / 16;      // 8 warps x 2 nodes -> 3125 blocks
    const int MB = (NN + 127) / 128;

    const uint4* WHI = (const uint4*)whi;
    const uint4* WLO = (const uint4*)wlo;

    gather_kernel<32><<<GB, 256>>>(h0h);
    mlp_mma<32, true, false><<<MB, 256, MLP_SMEM>>>(
        WHI + 0, WLO + 0, WHI + 512, WLO + 512, b1, b2, (__nv_bfloat162*)hA, batch);

    void* cur = hA;
    void* nxt = hB;
    for (int l = 1; l < LL; l++) {
        const uint4* w1h = WHI + (size_t)(l * 2) * 512;
        const uint4* w1l = WLO + (size_t)(l * 2) * 512;
        const uint4* w2h = WHI + (size_t)(l * 2 + 1) * 512;
        const uint4* w2l = WLO + (size_t)(l * 2 + 1) * 512;
        gather_kernel<64><<<GB, 256>>>(cur);
        if (l < LL - 1) {
            mlp_mma<64, true, false><<<MB, 256, MLP_SMEM>>>(
                w1h, w1l, w2h, w2l, b1 + l * 64, b2 + l * 64, (__nv_bfloat162*)nxt, batch);
            void* t = cur; cur = nxt; nxt = t;
        } else {
            mlp_mma<64, false, true><<<MB, 256, MLP_SMEM>>>(
                w1h, w1l, w2h, w2l, b1 + l * 64, b2 + l * 64, (__nv_bfloat162*)nxt, batch);
        }
    }

    final_kernel<<<(BB * 32 + 255) / 256, 256>>>(lin_w, lin_b, out);
}

// round 17
// speedup vs baseline: 1.1482x; 1.0070x over previous
#include <cuda_runtime.h>
#include <cuda_bf16.h>
#include <cstdint>

#define NN 50000
#define EE 800000
#define BB 50
#define LL 7
#define NSCAN_BLK 49

// ---------------- scratch (device globals; no allocations) ----------------
// g_cursor must be zero at entry each call (re-zeroed by scatter_fix).
// Row NN of h buffers is a dummy all-zero row (gather out-of-range target).
__device__ __nv_bfloat16  g_h0h[(NN + 1) * 32];
__device__ __nv_bfloat162 g_hA[(NN + 1) * 32];
__device__ __nv_bfloat162 g_hB[(NN + 1) * 32];
__device__ __nv_bfloat16  g_z[NN * 64];
__device__ __nv_bfloat16  g_Whi[LL * 2 * 4096];
__device__ __nv_bfloat16  g_Wlo[LL * 2 * 4096];
__device__ int   g_rowptr[NN + 1];
__device__ int   g_rowptr2[NN + 1];
__device__ int   g_cursor[NN];
__device__ int   g_rank[EE];
__device__ int   g_csr[EE + 16];     // +16 pad: steered probes may read past end
__device__ int   g_bsum[64];
__device__ float g_pool[BB * 64];
__device__ int   g_start[BB];
__device__ int   g_end[BB];

typedef unsigned long long u64;
__device__ __forceinline__ uint32_t smem_to_u32(const void* p) {
    uint32_t a;
    asm("{ .reg .u64 t; cvta.to.shared.u64 t, %1; cvt.u32.u64 %0, t; }" : "=r"(a) : "l"(p));
    return a;
}
__device__ __forceinline__ u64 add2(u64 a, u64 b) {
    u64 d; asm("add.rn.f32x2 %0,%1,%2;" : "=l"(d) : "l"(a), "l"(b)); return d;
}
__device__ __forceinline__ u64 bf2f2(uint32_t u) {
    uint32_t lo = u << 16, hi = u & 0xFFFF0000u;
    u64 r; asm("mov.b64 %0,{%1,%2};" : "=l"(r) : "r"(lo), "r"(hi)); return r;
}
__device__ __forceinline__ float2 unpk(u64 v) {
    float2 f; asm("mov.b64 {%0,%1},%2;" : "=f"(f.x), "=f"(f.y) : "l"(v)); return f;
}
__device__ __forceinline__ u64 shfl_xor64(u64 v, int m) {
    uint32_t lo, hi;
    asm("mov.b64 {%0,%1},%2;" : "=r"(lo), "=r"(hi) : "l"(v));
    lo = __shfl_xor_sync(0xffffffffu, lo, m);
    hi = __shfl_xor_sync(0xffffffffu, hi, m);
    u64 r; asm("mov.b64 %0,{%1,%2};" : "=l"(r) : "r"(lo), "r"(hi)); return r;
}
__device__ __forceinline__ uint32_t pkbf(u64 acc) {
    float2 f = unpk(acc);
    __nv_bfloat162 b = __float22bfloat162_rn(f);
    return *(uint32_t*)&b;
}
__device__ __forceinline__ float2 f2add(float2 a, float2 b) { a.x += b.x; a.y += b.y; return a; }

// ---------------- mma.sync helpers ----------------
__device__ __forceinline__ void ldsm_x4(uint32_t r[4], uint32_t addr) {
    asm volatile("ldmatrix.sync.aligned.m8n8.x4.shared.b16 {%0,%1,%2,%3}, [%4];"
        : "=r"(r[0]), "=r"(r[1]), "=r"(r[2]), "=r"(r[3]) : "r"(addr));
}
__device__ __forceinline__ void ldsm_x2(uint32_t r[2], uint32_t addr) {
    asm volatile("ldmatrix.sync.aligned.m8n8.x2.shared.b16 {%0,%1}, [%2];"
        : "=r"(r[0]), "=r"(r[1]) : "r"(addr));
}
__device__ __forceinline__ void mma16816(float d[4], const uint32_t a[4], const uint32_t b[2]) {
    asm volatile(
        "mma.sync.aligned.m16n8k16.row.col.f32.bf16.bf16.f32 "
        "{%0,%1,%2,%3}, {%4,%5,%6,%7}, {%8,%9}, {%0,%1,%2,%3};"
        : "+f"(d[0]), "+f"(d[1]), "+f"(d[2]), "+f"(d[3])
        : "r"(a[0]), "r"(a[1]), "r"(a[2]), "r"(a[3]), "r"(b[0]), "r"(b[1]));
}

// ---------------- launch 1: init + h0 + histogram + weight pre-split ----------------
__global__ void fused_init(const float* __restrict__ x, const float* __restrict__ pos,
                           const int* __restrict__ batch, const int* __restrict__ dst,
                           const float* __restrict__ W1f, const float* __restrict__ W1r,
                           const float* __restrict__ W2) {
    int i = blockIdx.x * blockDim.x + threadIdx.x;
    if (i < NN * 32) {
        int v = i >> 5, c = i & 31;
        float val = (c < 29) ? x[v * 29 + c] : pos[v * 3 + (c - 29)];
        g_h0h[i] = __float2bfloat16_rn(val);
    }
    if (i < EE) g_rank[i] = atomicAdd(&g_cursor[dst[i]], 1);
    if (i < NN) {
        int bi = __ldg(&batch[i]);
        if (i == 0 || __ldg(&batch[i - 1]) != bi) g_start[bi] = i;
        if (i == NN - 1 || __ldg(&batch[i + 1]) != bi) g_end[bi] = i + 1;
    }
    if (i < 2 * LL * 4096) {
        int l = i >> 13, m = (i >> 12) & 1, fc = i & 4095;
        int f = fc >> 6, c = fc & 63;
        float w = 0.f;
        if (m == 0) {
            if (l == 0) { if (c < 32) w = __ldg(&W1f[c * 64 + f]); }
            else w = __ldg(&W1r[(size_t)(l - 1) * 4096 + c * 64 + f]);
        } else {
            w = __ldg(&W2[(size_t)l * 4096 + c * 64 + f]);
        }
        __nv_bfloat16 hi = __float2bfloat16_rn(w);
        g_Whi[i] = hi;
        g_Wlo[i] = __float2bfloat16_rn(w - __bfloat162float(hi));
    }
    if (i < 32) {
        g_h0h[NN * 32 + i] = __float2bfloat16_rn(0.f);
        __nv_bfloat162 z2 = __float22bfloat162_rn(make_float2(0.f, 0.f));
        g_hA[NN * 32 + i] = z2;
        g_hB[NN * 32 + i] = z2;
    }
    if (i == 0) g_rowptr[0] = 0;
    if (i < BB * 64) g_pool[i] = 0.f;
}

// ---------------- launch 2: per-block scan of degrees ----------------
__global__ void scanA_kernel() {
    __shared__ int wsum[32];
    int i = blockIdx.x * 1024 + threadIdx.x;
    int lane = threadIdx.x & 31, wid = threadIdx.x >> 5;
    int xx = (i < NN) ? g_cursor[i] : 0;
    #pragma unroll
    for (int o = 1; o < 32; o <<= 1) {
        int y = __shfl_up_sync(0xffffffffu, xx, o);
        if (lane >= o) xx += y;
    }
    if (lane == 31) wsum[wid] = xx;
    __syncthreads();
    if (wid == 0) {
        int s = wsum[lane];
        #pragma unroll
        for (int o = 1; o < 32; o <<= 1) {
            int y = __shfl_up_sync(0xffffffffu, s, o);
            if (lane >= o) s += y;
        }
        wsum[lane] = s;
    }
    __syncthreads();
    int incl = xx + (wid ? wsum[wid - 1] : 0);
    if (i < NN) g_rowptr[i + 1] = incl;
    if (threadIdx.x == 1023) g_bsum[blockIdx.x] = incl;
}

// ---------------- launch 3: scatter + rowptr finalize + cursor re-zero ----------------
__global__ void scatter_fix(const int* __restrict__ src, const int* __restrict__ dst) {
    __shared__ int sb[NSCAN_BLK + 1];
    if (threadIdx.x < NSCAN_BLK) sb[threadIdx.x + 1] = g_bsum[threadIdx.x];
    __syncthreads();
    if (threadIdx.x == 0) {
        int run = 0;
        #pragma unroll
        for (int k = 0; k < NSCAN_BLK; k++) { int t = sb[k + 1]; sb[k] = run; run += t; }
    }
    __syncthreads();
    int e = blockIdx.x * blockDim.x + threadIdx.x;
    if (e <= NN) {
        int add = (e > 0) ? sb[(e - 1) >> 10] : 0;
        g_rowptr2[e] = g_rowptr[e] + add;
    }
    if (e < EE) {
        int d = dst[e];
        int base = g_rowptr[d] + ((d > 0) ? sb[(d - 1) >> 10] : 0);
        g_csr[base + g_rank[e]] = src[e];
    }
    if (e < NN) g_cursor[e] = 0;
}

// ---------------- gather: 1 node/warp, no SMEM, direct csr reads ----------------
// 8 lanes per row-slice (q), 4 edge slots (slot). Each csr index is read once
// (8-lane broadcast = 1 sector). Out-of-range slots steered to zero row NN.
template <int C>
__global__ void __launch_bounds__(256, 8) gather_kernel(const void* __restrict__ h_in_v) {
    const int lane = threadIdx.x & 31;
    const int slot = lane >> 3, q = lane & 7;
    const int v = blockIdx.x * 8 + (threadIdx.x >> 5);
    if (v >= NN) return;

    const int r0 = __ldg(&g_rowptr2[v]);
    const int deg = __ldg(&g_rowptr2[v + 1]) - r0;
    const int* cp = g_csr + r0;

    if (C == 64) {
        const uint4* hp = (const uint4*)h_in_v;
        uint4 rs = make_uint4(0, 0, 0, 0);
        if (slot == 0) rs = __ldg(hp + (size_t)v * 8 + q);
        u64 a0 = bf2f2(rs.x), a1 = bf2f2(rs.y), a2 = bf2f2(rs.z), a3 = bf2f2(rs.w);
        #pragma unroll 2
        for (int j0 = 0; j0 < deg; j0 += 4) {
            int j = j0 + slot;
            int sv = __ldg(cp + j);          // padded; junk discarded by SEL
            int idx = (j < deg) ? sv : NN;   // NN = zero row
            uint4 r = __ldg(hp + (size_t)idx * 8 + q);
            a0 = add2(a0, bf2f2(r.x));
            a1 = add2(a1, bf2f2(r.y));
            a2 = add2(a2, bf2f2(r.z));
            a3 = add2(a3, bf2f2(r.w));
        }
        #pragma unroll
        for (int m = 8; m <= 16; m <<= 1) {
            a0 = add2(a0, shfl_xor64(a0, m));
            a1 = add2(a1, shfl_xor64(a1, m));
            a2 = add2(a2, shfl_xor64(a2, m));
            a3 = add2(a3, shfl_xor64(a3, m));
        }
        if (slot == 0) {
            uint4 o = make_uint4(pkbf(a0), pkbf(a1), pkbf(a2), pkbf(a3));
            ((uint4*)g_z)[(size_t)v * 8 + q] = o;
        }
    } else {
        const uint2* hp = (const uint2*)h_in_v;
        uint2 rs = make_uint2(0, 0);
        if (slot == 0) rs = __ldg(hp + (size_t)v * 8 + q);
        u64 a0 = bf2f2(rs.x), a1 = bf2f2(rs.y);
        #pragma unroll 2
        for (int j0 = 0; j0 < deg; j0 += 4) {
            int j = j0 + slot;
            int sv = __ldg(cp + j);
            int idx = (j < deg) ? sv : NN;
            uint2 r = __ldg(hp + (size_t)idx * 8 + q);
            a0 = add2(a0, bf2f2(r.x));
            a1 = add2(a1, bf2f2(r.y));
        }
        #pragma unroll
        for (int m = 8; m <= 16; m <<= 1) {
            a0 = add2(a0, shfl_xor64(a0, m));
            a1 = add2(a1, shfl_xor64(a1, m));
        }
        if (slot == 0) {
            uint2 o = make_uint2(pkbf(a0), pkbf(a1));
            ((uint2*)g_z)[(size_t)v * 16 + q] = o;
        }
    }
}

// ---------------- MLP via mma.sync (one CTA = 128 nodes, 8 warps x 16) ----------------
#define OFF_ZT   0
#define OFF_W1HI 18432
#define OFF_W1LO 27648
#define OFF_W2HI 36864
#define OFF_W2LO 46080
#define OFF_B1   55296
#define OFF_B2   55552
#define MLP_SMEM 55808

template <int KCH>
__device__ __forceinline__ void gemv16(uint32_t a_base, uint32_t whi, uint32_t wlo,
                                       float acc[8][4], int lane) {
    uint32_t a[KCH][4];
    uint32_t arow = a_base + (lane & 15) * 144 + ((lane >> 4) << 4);
    #pragma unroll
    for (int kc = 0; kc < KCH; kc++) ldsm_x4(a[kc], arow + kc * 32);
    uint32_t bro = (lane & 7) * 144 + ((lane & 8) ? 16 : 0);
    #pragma unroll
    for (int nc = 0; nc < 8; nc++) {
        #pragma unroll
        for (int i = 0; i < 4; i++) acc[nc][i] = 0.f;
        #pragma unroll
        for (int kc = 0; kc < KCH; kc++) {
            uint32_t bh[2], bl[2];
            ldsm_x2(bh, whi + bro + nc * 1152 + kc * 32);
            mma16816(acc[nc], a[kc], bh);
            ldsm_x2(bl, wlo + bro + nc * 1152 + kc * 32);
            mma16816(acc[nc], a[kc], bl);
        }
    }
}

template <int C, bool RELU_OUT, bool LAST>
__global__ void __launch_bounds__(256) mlp_mma(
    const uint4* __restrict__ w1hi, const uint4* __restrict__ w1lo,
    const uint4* __restrict__ w2hi, const uint4* __restrict__ w2lo,
    const float* __restrict__ b1, const float* __restrict__ b2,
    __nv_bfloat162* __restrict__ h_out, const int* __restrict__ batch)
{
    extern __shared__ char smem[];
    const uint32_t sb = smem_to_u32(smem);
    const int tid = threadIdx.x, wid = tid >> 5, lane = tid & 31;
    const int vbase = blockIdx.x * 128;
    const int wrow = wid * 16;

    for (int i = tid; i < 512; i += 256) {
        int f = i >> 3, j = i & 7;
        uint32_t d = f * 144 + j * 16;
        *(uint4*)(smem + OFF_W1HI + d) = __ldg(w1hi + i);
        *(uint4*)(smem + OFF_W1LO + d) = __ldg(w1lo + i);
        *(uint4*)(smem + OFF_W2HI + d) = __ldg(w2hi + i);
        *(uint4*)(smem + OFF_W2LO + d) = __ldg(w2lo + i);
    }
    if (tid < 64) {
        ((float*)(smem + OFF_B1))[tid] = __ldg(&b1[tid]);
        ((float*)(smem + OFF_B2))[tid] = __ldg(&b2[tid]);
    }

    constexpr int BPR = C / 8;
    for (int i = tid; i < 128 * BPR; i += 256) {
        int row = i / BPR, j = i % BPR;
        int v = vbase + row;
        uint4 val = make_uint4(0, 0, 0, 0);
        if (v < NN) val = __ldg((const uint4*)g_z + (size_t)v * 8 + j);
        *(uint4*)(smem + OFF_ZT + row * 144 + j * 16) = val;
    }
    __syncthreads();

    float acc[8][4];
    const uint32_t abase = sb + OFF_ZT + wrow * 144;

    gemv16<C / 16>(abase, sb + OFF_W1HI, sb + OFF_W1LO, acc, lane);
    {
        const float* b1s = (const float*)(smem + OFF_B1);
        int r0off = (wrow + (lane >> 2)) * 144;
        int cb = 2 * (lane & 3);
        #pragma unroll
        for (int nc = 0; nc < 8; nc++) {
            int n0 = nc * 8 + cb;
            float bx = b1s[n0], by = b1s[n0 + 1];
            __nv_bfloat162 p0 = __float22bfloat162_rn(
                make_float2(fmaxf(acc[nc][0] + bx, 0.f), fmaxf(acc[nc][1] + by, 0.f)));
            __nv_bfloat162 p1 = __float22bfloat162_rn(
                make_float2(fmaxf(acc[nc][2] + bx, 0.f), fmaxf(acc[nc][3] + by, 0.f)));
            *(uint32_t*)(smem + OFF_ZT + r0off + n0 * 2) = *(uint32_t*)&p0;
            *(uint32_t*)(smem + OFF_ZT + r0off + 8 * 144 + n0 * 2) = *(uint32_t*)&p1;
        }
    }
    __syncwarp();

    gemv16<4>(abase, sb + OFF_W2HI, sb + OFF_W2LO, acc, lane);
    {
        const float* b2s = (const float*)(smem + OFF_B2);
        int r0 = wrow + (lane >> 2);
        int v0 = vbase + r0, v1 = v0 + 8;
        int cb = 2 * (lane & 3);
        if (LAST) {
            int vA = vbase + wrow;
            bool uni = (vA + 15 < NN) && (__ldg(&batch[vA]) == __ldg(&batch[vA + 15]));
            if (uni) {
                int g = __ldg(&batch[vA]);
                float sx[8], sy[8];
                #pragma unroll
                for (int nc = 0; nc < 8; nc++) {
                    int n0 = nc * 8 + cb;
                    sx[nc] = acc[nc][0] + acc[nc][2] + 2.f * b2s[n0];
                    sy[nc] = acc[nc][1] + acc[nc][3] + 2.f * b2s[n0 + 1];
                }
                #pragma unroll
                for (int m = 4; m <= 16; m <<= 1) {
                    #pragma unroll
                    for (int nc = 0; nc < 8; nc++) {
                        sx[nc] += __shfl_xor_sync(0xffffffffu, sx[nc], m);
                        sy[nc] += __shfl_xor_sync(0xffffffffu, sy[nc], m);
                    }
                }
                if ((lane >> 2) == 0) {
                    #pragma unroll
                    for (int nc = 0; nc < 8; nc++) {
                        int n0 = nc * 8 + cb;
                        atomicAdd((float2*)&g_pool[g * 64 + n0], make_float2(sx[nc], sy[nc]));
                    }
                }
            } else {
                int gb0 = (v0 < NN) ? __ldg(&batch[v0]) : 0;
                int gb1 = (v1 < NN) ? __ldg(&batch[v1]) : 0;
                #pragma unroll
                for (int nc = 0; nc < 8; nc++) {
                    int n0 = nc * 8 + cb;
                    float bx = b2s[n0], by = b2s[n0 + 1];
                    if (v0 < NN)
                        atomicAdd((float2*)&g_pool[gb0 * 64 + n0],
                                  make_float2(acc[nc][0] + bx, acc[nc][1] + by));
                    if (v1 < NN)
                        atomicAdd((float2*)&g_pool[gb1 * 64 + n0],
                                  make_float2(acc[nc][2] + bx, acc[nc][3] + by));
                }
            }
        } else {
            #pragma unroll
            for (int nc = 0; nc < 8; nc++) {
                int n0 = nc * 8 + cb;
                float bx = b2s[n0], by = b2s[n0 + 1];
                float x0 = acc[nc][0] + bx, y0 = acc[nc][1] + by;
                float x1 = acc[nc][2] + bx, y1 = acc[nc][3] + by;
                if (RELU_OUT) {
                    x0 = fmaxf(x0, 0.f); y0 = fmaxf(y0, 0.f);
                    x1 = fmaxf(x1, 0.f); y1 = fmaxf(y1, 0.f);
                }
                __nv_bfloat162 p0 = __float22bfloat162_rn(make_float2(x0, y0));
                __nv_bfloat162 p1 = __float22bfloat162_rn(make_float2(x1, y1));
                if (v0 < NN) *((uint32_t*)h_out + (size_t)v0 * 32 + (n0 >> 1)) = *(uint32_t*)&p0;
                if (v1 < NN) *((uint32_t*)h_out + (size_t)v1 * 32 + (n0 >> 1)) = *(uint32_t*)&p1;
            }
        }
    }
}

// ---------------- final linear ----------------
__global__ void final_kernel(const float* __restrict__ lin_w,
                             const float* __restrict__ lin_b,
                             float* __restrict__ out) {
    int gtid = blockIdx.x * blockDim.x + threadIdx.x;
    int g = gtid >> 5, lane = threadIdx.x & 31;
    if (g >= BB) return;
    float s = g_pool[g * 64 + lane] * __ldg(&lin_w[lane]) +
              g_pool[g * 64 + 32 + lane] * __ldg(&lin_w[32 + lane]);
    #pragma unroll
    for (int o = 16; o; o >>= 1) s += __shfl_xor_sync(0xffffffffu, s, o);
    if (lane == 0) {
        float cnt = (float)(g_end[g] - g_start[g]);
        out[g] = s / fmaxf(cnt, 1.f) + lin_b[0];
    }
}

// ---------------- launch ----------------
extern "C" void kernel_launch(void* const* d_in, const int* in_sizes, int n_in,
                              void* d_out, int out_size) {
    const float* x     = (const float*)d_in[0];
    const float* pos   = (const float*)d_in[1];
    const int*   ei    = (const int*)d_in[2];
    const int*   batch = (const int*)d_in[3];
    const float* W1f   = (const float*)d_in[4];
    const float* W1r   = (const float*)d_in[5];
    const float* b1    = (const float*)d_in[6];
    const float* W2    = (const float*)d_in[7];
    const float* b2    = (const float*)d_in[8];
    const float* lin_w = (const float*)d_in[9];
    const float* lin_b = (const float*)d_in[10];
    float* out = (float*)d_out;

    const int* src = ei;
    const int* dst = ei + EE;

    void *h0h, *hA, *hB, *whi, *wlo;
    cudaGetSymbolAddress(&h0h, g_h0h);
    cudaGetSymbolAddress(&hA, g_hA);
    cudaGetSymbolAddress(&hB, g_hB);
    cudaGetSymbolAddress(&whi, g_Whi);
    cudaGetSymbolAddress(&wlo, g_Wlo);

    cudaFuncSetAttribute((const void*)mlp_mma<32, true,  false>, cudaFuncAttributeMaxDynamicSharedMemorySize, MLP_SMEM);
    cudaFuncSetAttribute((const void*)mlp_mma<64, true,  false>, cudaFuncAttributeMaxDynamicSharedMemorySize, MLP_SMEM);
    cudaFuncSetAttribute((const void*)mlp_mma<64, false, true>,  cudaFuncAttributeMaxDynamicSharedMemorySize, MLP_SMEM);

    fused_init<<<(NN * 32 + 255) / 256, 256>>>(x, pos, batch, dst, W1f, W1r, W2);
    scanA_kernel<<<NSCAN_BLK, 1024>>>();
    scatter_fix<<<(EE + 255) / 256, 256>>>(src, dst);

    const int GB = (NN + 7) / 8;        // 1 node/warp -> 6250 blocks
    const int MB = (NN + 127) / 128;

    const uint4* WHI = (const uint4*)whi;
    const uint4* WLO = (const uint4*)wlo;

    gather_kernel<32><<<GB, 256>>>(h0h);
    mlp_mma<32, true, false><<<MB, 256, MLP_SMEM>>>(
        WHI + 0, WLO + 0, WHI + 512, WLO + 512, b1, b2, (__nv_bfloat162*)hA, batch);

    void* cur = hA;
    void* nxt = hB;
    for (int l = 1; l < LL; l++) {
        const uint4* w1h = WHI + (size_t)(l * 2) * 512;
        const uint4* w1l = WLO + (size_t)(l * 2) * 512;
        const uint4* w2h = WHI + (size_t)(l * 2 + 1) * 512;
        const uint4* w2l = WLO + (size_t)(l * 2 + 1) * 512;
        gather_kernel<64><<<GB, 256>>>(cur);
        if (l < LL - 1) {
            mlp_mma<64, true, false><<<MB, 256, MLP_SMEM>>>(
                w1h, w1l, w2h, w2l, b1 + l * 64, b2 + l * 64, (__nv_bfloat162*)nxt, batch);
            void* t = cur; cur = nxt; nxt = t;
        } else {
            mlp_mma<64, false, true><<<MB, 256, MLP_SMEM>>>(
                w1h, w1l, w2h, w2l, b1 + l * 64, b2 + l * 64, (__nv_bfloat162*)nxt, batch);
        }
    }

    final_kernel<<<(BB * 32 + 255) / 256, 256>>>(lin_w, lin_b, out);
}